// round 11
// baseline (speedup 1.0000x reference)
#include <cuda_runtime.h>
#include <math.h>
#include <stdint.h>

#define NN 50000
#define EE 800000
#define IN_DIM 200
#define HD 128
#define DD 127
#define GG 512
#define EPSF 1e-5f

// ---------------- scratch (device globals; no allocation allowed) ----------------
__device__ float g_h[NN * HD];      // hyperboloid node features
__device__ float g_u[NN * HD];      // logmap0 spatial (slots 0..126, slot127 = 0)
__device__ float g_p[NN * HD];      // GEMM output
__device__ float g_hl[NN * HD];     // attention-linear hyperboloid points
__device__ float g_wt[6 * HD * HD];   // transposed+padded weights (k-major)
__device__ float g_wtin[IN_DIM * HD];
__device__ float g_wf[6 * 8 * 16 * 32 * 4];     // bf16-split fragment weights (K=128 mats)
__device__ float g_wfin[13 * 16 * 32 * 4];      // bf16-split fragment input weights (K=200->208)
__device__ int   g_cnt[NN];
__device__ int   g_rowptr[NN + 1];
__device__ int   g_cur[NN];
__device__ int   g_dstidx[EE];
__device__ int   g_blksum[256];
__device__ int   g_blkoff[256];

__device__ __forceinline__ float warp_sum(float v) {
#pragma unroll
    for (int o = 16; o; o >>= 1) v += __shfl_xor_sync(0xffffffffu, v, o);
    return v;
}

__device__ __forceinline__ void red_v4(float* p, float a, float b, float c, float d) {
    asm volatile("red.global.add.v4.f32 [%0], {%1,%2,%3,%4};"
                 :: "l"(p), "f"(a), "f"(b), "f"(c), "f"(d) : "memory");
}

// m16n8k16 bf16 MMA, fp32 accumulate (A row-major frag, B col-major frag)
__device__ __forceinline__ void mma_bf16(float* d, uint32_t a0, uint32_t a1,
                                         uint32_t a2, uint32_t a3,
                                         uint32_t b0, uint32_t b1) {
    asm("mma.sync.aligned.m16n8k16.row.col.f32.bf16.bf16.f32 "
        "{%0,%1,%2,%3}, {%4,%5,%6,%7}, {%8,%9}, {%0,%1,%2,%3};"
        : "+f"(d[0]), "+f"(d[1]), "+f"(d[2]), "+f"(d[3])
        : "r"(a0), "r"(a1), "r"(a2), "r"(a3), "r"(b0), "r"(b1));
}

// pack two floats into bf16x2 (lower half = x, upper half = y), round-to-nearest
__device__ __forceinline__ uint32_t bf16x2_hi(float x, float y) {
    uint32_t r;
    asm("cvt.rn.bf16x2.f32 %0, %1, %2;" : "=r"(r) : "f"(y), "f"(x));
    return r;
}
// residual pair: lo = f - float(bf16 hi), packed bf16x2
__device__ __forceinline__ uint32_t bf16x2_lo(float x, float y, uint32_t h) {
    float h0 = __uint_as_float(h << 16);
    float h1 = __uint_as_float(h & 0xFFFF0000u);
    return bf16x2_hi(x - h0, y - h1);
}

// ---------------- utility kernels ----------------
__global__ void zero4_kernel(float4* __restrict__ p, int n4) {
    int i = blockIdx.x * blockDim.x + threadIdx.x;
    if (i < n4) p[i] = make_float4(0.f, 0.f, 0.f, 0.f);
}

__global__ void zeroi_kernel(int* __restrict__ p, int n) {
    int i = blockIdx.x * blockDim.x + threadIdx.x;
    if (i < n) p[i] = 0;
}

__global__ void prep_weights(const float* __restrict__ att_w, const float* __restrict__ mlp_w) {
    int idx = blockIdx.x * blockDim.x + threadIdx.x;
    if (idx >= 6 * HD * HD) return;
    int w = idx >> 14;
    int k = (idx >> 7) & 127;
    int j = idx & 127;
    float val = 0.f;
    if (k < DD && j < DD) {
        const float* src = (w < 2) ? (att_w + w * DD * DD) : (mlp_w + (w - 2) * DD * DD);
        val = src[j * DD + k];
    }
    g_wt[idx] = val;
}

__global__ void prep_win(const float* __restrict__ w_in) {
    int idx = blockIdx.x * blockDim.x + threadIdx.x;
    if (idx >= IN_DIM * HD) return;
    int k = idx >> 7;
    int j = idx & 127;
    g_wtin[idx] = (j < DD) ? w_in[k * DD + j] : 0.f;
}

// bf16-split fragment weights: uint4 (b0h, b1h, b0l, b1l) per (mat, k16, tile, lane)
__global__ void prep_wf() {
    int idx = blockIdx.x * blockDim.x + threadIdx.x;
    if (idx >= 6 * 8 * 16 * 32) return;
    int lane = idx & 31;
    int tile = (idx >> 5) & 15;
    int k16 = (idx >> 9) & 7;
    int mat = idx >> 12;
    int gg = lane >> 2, t4 = lane & 3;
    int k0 = k16 * 16 + 2 * t4;
    int n = tile * 8 + gg;
    const float* W = g_wt + mat * HD * HD;
    float w00 = W[k0 * HD + n],       w01 = W[(k0 + 1) * HD + n];
    float w10 = W[(k0 + 8) * HD + n], w11 = W[(k0 + 9) * HD + n];
    uint4 o;
    o.x = bf16x2_hi(w00, w01);
    o.y = bf16x2_hi(w10, w11);
    o.z = bf16x2_lo(w00, w01, o.x);
    o.w = bf16x2_lo(w10, w11, o.y);
    ((uint4*)g_wf)[idx] = o;
}

__global__ void prep_wfin() {
    int idx = blockIdx.x * blockDim.x + threadIdx.x;
    if (idx >= 13 * 16 * 32) return;
    int lane = idx & 31;
    int tile = (idx >> 5) & 15;
    int k16 = idx >> 9;                 // 0..12
    int gg = lane >> 2, t4 = lane & 3;
    int k0 = k16 * 16 + 2 * t4;
    int n = tile * 8 + gg;
    float w00 = (k0 < IN_DIM)     ? g_wtin[k0 * HD + n] : 0.f;
    float w01 = (k0 + 1 < IN_DIM) ? g_wtin[(k0 + 1) * HD + n] : 0.f;
    float w10 = (k0 + 8 < IN_DIM) ? g_wtin[(k0 + 8) * HD + n] : 0.f;
    float w11 = (k0 + 9 < IN_DIM) ? g_wtin[(k0 + 9) * HD + n] : 0.f;
    uint4 o;
    o.x = bf16x2_hi(w00, w01);
    o.y = bf16x2_hi(w10, w11);
    o.z = bf16x2_lo(w00, w01, o.x);
    o.w = bf16x2_lo(w10, w11, o.y);
    ((uint4*)g_wfin)[idx] = o;
}

// ---------------- CSR build ----------------
__global__ void hist_kernel(const int* __restrict__ ei) {
    int e = blockIdx.x * blockDim.x + threadIdx.x;
    if (e < EE) atomicAdd(&g_cnt[ei[e]], 1);
}

__global__ void scan1_kernel() {
    __shared__ int sh[256];
    int t = threadIdx.x;
    int idx = blockIdx.x * 256 + t;
    int v = (idx < NN) ? g_cnt[idx] : 0;
    sh[t] = v;
    __syncthreads();
#pragma unroll
    for (int d = 1; d < 256; d <<= 1) {
        int o = (t >= d) ? sh[t - d] : 0;
        __syncthreads();
        sh[t] += o;
        __syncthreads();
    }
    if (idx < NN) g_rowptr[idx] = sh[t] - v;
    if (t == 255) g_blksum[blockIdx.x] = sh[255];
}

__global__ void scan2_kernel(int nblk) {
    __shared__ int sh[256];
    int t = threadIdx.x;
    int v = (t < nblk) ? g_blksum[t] : 0;
    sh[t] = v;
    __syncthreads();
#pragma unroll
    for (int d = 1; d < 256; d <<= 1) {
        int o = (t >= d) ? sh[t - d] : 0;
        __syncthreads();
        sh[t] += o;
        __syncthreads();
    }
    if (t < nblk) g_blkoff[t] = sh[t] - v;
    if (t == 255) g_rowptr[NN] = sh[255];
}

__global__ void scan3_kernel() {
    int idx = blockIdx.x * 256 + threadIdx.x;
    if (idx >= NN) return;
    int r = g_rowptr[idx] + g_blkoff[blockIdx.x];
    g_rowptr[idx] = r;
    g_cur[idx] = r;
}

__global__ void scatter_kernel(const int* __restrict__ ei) {
    int e = blockIdx.x * blockDim.x + threadIdx.x;
    if (e >= EE) return;
    int s = ei[e];
    int pos = atomicAdd(&g_cur[s], 1);
    g_dstidx[pos] = ei[EE + e];
}

// ---------------- split-bf16 TC GEMM, K=128, smem-staged A ----------------
// A tile (64 rows x 128 cols) staged once per block as packed bf16x2 hi/lo in
// smem (row stride 68 words -> fragment reads provably bank-conflict-free:
// bank = (4*row + word) mod 32, 8 rows x 4 words cover all 32 banks).
// Conversion happens once per element (was duplicated across wn warps).
#define ASTRIDE 68
template <bool HASBIAS>
__global__ void __launch_bounds__(256) gemm_tc128(const float* __restrict__ U,
                                                  const uint4* __restrict__ WF,
                                                  const float* __restrict__ bias,
                                                  float* __restrict__ P) {
    __shared__ uint32_t sh_hi[64 * ASTRIDE];
    __shared__ uint32_t sh_lo[64 * ASTRIDE];
    int tid = threadIdx.x;
    int lane = tid & 31;
    int w = tid >> 5;
    int wm = w & 3;
    int wn = w >> 2;
    int row0 = blockIdx.x * 64;
    int gg = lane >> 2, t4 = lane & 3;

    // stage A: coalesced float2 loads, convert once, packed store
    for (int idx = tid; idx < 64 * 64; idx += 256) {
        int row = idx >> 6, word = idx & 63;
        int gr = row0 + row;
        float2 f = (gr < NN) ? *(const float2*)&U[(size_t)gr * HD + word * 2]
                             : make_float2(0.f, 0.f);
        uint32_t h = bf16x2_hi(f.x, f.y);
        sh_hi[row * ASTRIDE + word] = h;
        sh_lo[row * ASTRIDE + word] = bf16x2_lo(f.x, f.y, h);
    }
    __syncthreads();

    int ral = 16 * wm + gg;    // local rows of this thread's fragments
    int rbl = ral + 8;

    float acc[8][4];
#pragma unroll
    for (int t = 0; t < 8; t++) {
        acc[t][0] = 0.f; acc[t][1] = 0.f; acc[t][2] = 0.f; acc[t][3] = 0.f;
    }

    for (int k16 = 0; k16 < 8; k16++) {
        int wb = k16 * 8 + t4;
        uint32_t h0 = sh_hi[ral * ASTRIDE + wb];
        uint32_t h1 = sh_hi[rbl * ASTRIDE + wb];
        uint32_t h2 = sh_hi[ral * ASTRIDE + wb + 4];
        uint32_t h3 = sh_hi[rbl * ASTRIDE + wb + 4];
        uint32_t l0 = sh_lo[ral * ASTRIDE + wb];
        uint32_t l1 = sh_lo[rbl * ASTRIDE + wb];
        uint32_t l2 = sh_lo[ral * ASTRIDE + wb + 4];
        uint32_t l3 = sh_lo[rbl * ASTRIDE + wb + 4];
        const uint4* wf = WF + ((size_t)k16 * 16 + wn * 8) * 32 + lane;
#pragma unroll
        for (int t = 0; t < 8; t++) {
            uint4 bv = wf[t * 32];   // (b0h, b1h, b0l, b1l)
            mma_bf16(acc[t], h0, h1, h2, h3, bv.x, bv.y);  // hi*hi
            mma_bf16(acc[t], h0, h1, h2, h3, bv.z, bv.w);  // hi*lo
            mma_bf16(acc[t], l0, l1, l2, l3, bv.x, bv.y);  // lo*hi
        }
    }

    int ra = row0 + ral;
    int rb = row0 + rbl;
#pragma unroll
    for (int t = 0; t < 8; t++) {
        int j0 = 64 * wn + 8 * t + 2 * t4;   // even, 0..126
        float b0 = 0.f, b1 = 0.f;
        if (HASBIAS) {
            b0 = bias[j0];
            b1 = (j0 + 1 < DD) ? bias[j0 + 1] : 0.f;
        }
        float d0 = acc[t][0] + b0, d1 = acc[t][1] + b1;
        float d2 = acc[t][2] + b0, d3 = acc[t][3] + b1;
        if (j0 + 1 == 127) { d1 = 0.f; d3 = 0.f; }  // padding col
        if (ra < NN) *(float2*)&P[(size_t)ra * HD + j0] = make_float2(d0, d1);
        if (rb < NN) *(float2*)&P[(size_t)rb * HD + j0] = make_float2(d2, d3);
    }
}

// ---------------- input GEMM K=200 (R9 direct path, runs once) ----------------
__global__ void __launch_bounds__(256) gemm_tc_in(const float* __restrict__ U,
                                                  const uint4* __restrict__ WF,
                                                  float* __restrict__ P) {
    constexpr int K = IN_DIM;
    constexpr int K16 = (K + 15) / 16;   // 13
    int tid = threadIdx.x;
    int lane = tid & 31;
    int w = tid >> 5;
    int wm = w & 3;
    int wn = w >> 2;
    int row0 = blockIdx.x * 64;
    int gg = lane >> 2, t4 = lane & 3;
    int ra = row0 + 16 * wm + gg;
    int rb = ra + 8;
    const float* A0 = U + (size_t)min(ra, NN - 1) * K;
    const float* A1 = U + (size_t)min(rb, NN - 1) * K;

    float acc[8][4];
#pragma unroll
    for (int t = 0; t < 8; t++) {
        acc[t][0] = 0.f; acc[t][1] = 0.f; acc[t][2] = 0.f; acc[t][3] = 0.f;
    }

    for (int k16 = 0; k16 < K16; k16++) {
        int kc = k16 * 16;
        int c0 = kc + 2 * t4;
        int c1 = kc + 8 + 2 * t4;
        float2 fa0, fa1, fa2, fa3;
        if (k16 == K16 - 1) {
            fa0.x = (c0 < K) ? A0[c0] : 0.f;     fa0.y = (c0 + 1 < K) ? A0[c0 + 1] : 0.f;
            fa1.x = (c0 < K) ? A1[c0] : 0.f;     fa1.y = (c0 + 1 < K) ? A1[c0 + 1] : 0.f;
            fa2.x = (c1 < K) ? A0[c1] : 0.f;     fa2.y = (c1 + 1 < K) ? A0[c1 + 1] : 0.f;
            fa3.x = (c1 < K) ? A1[c1] : 0.f;     fa3.y = (c1 + 1 < K) ? A1[c1 + 1] : 0.f;
        } else {
            fa0 = *(const float2*)&A0[c0];
            fa1 = *(const float2*)&A1[c0];
            fa2 = *(const float2*)&A0[c1];
            fa3 = *(const float2*)&A1[c1];
        }
        uint32_t h0 = bf16x2_hi(fa0.x, fa0.y), h1 = bf16x2_hi(fa1.x, fa1.y);
        uint32_t h2 = bf16x2_hi(fa2.x, fa2.y), h3 = bf16x2_hi(fa3.x, fa3.y);
        uint32_t l0 = bf16x2_lo(fa0.x, fa0.y, h0), l1 = bf16x2_lo(fa1.x, fa1.y, h1);
        uint32_t l2 = bf16x2_lo(fa2.x, fa2.y, h2), l3 = bf16x2_lo(fa3.x, fa3.y, h3);
        const uint4* wf = WF + ((size_t)k16 * 16 + wn * 8) * 32 + lane;
#pragma unroll
        for (int t = 0; t < 8; t++) {
            uint4 bv = wf[t * 32];
            mma_bf16(acc[t], h0, h1, h2, h3, bv.x, bv.y);
            mma_bf16(acc[t], h0, h1, h2, h3, bv.z, bv.w);
            mma_bf16(acc[t], l0, l1, l2, l3, bv.x, bv.y);
        }
    }

#pragma unroll
    for (int t = 0; t < 8; t++) {
        int j0 = 64 * wn + 8 * t + 2 * t4;
        float d0 = acc[t][0], d1 = acc[t][1];
        float d2 = acc[t][2], d3 = acc[t][3];
        if (j0 + 1 == 127) { d1 = 0.f; d3 = 0.f; }
        if (ra < NN) *(float2*)&P[(size_t)ra * HD + j0] = make_float2(d0, d1);
        if (rb < NN) *(float2*)&P[(size_t)rb * HD + j0] = make_float2(d2, d3);
    }
}

// ---------------- warp-per-node elementwise kernels (unchanged) ----------------

__device__ __forceinline__ float4 logmap_quad(float4 o, float ss, float x0,
                                              float c, float sc, int lane) {
    float yn = fmaxf(sqrtf(ss), 1e-9f);
    float d = sc * acoshf(fmaxf(x0 / sc, 1.f + EPSF));
    float a = d / yn;
    float nx = __shfl_down_sync(0xffffffffu, o.x, 1);
    float4 u;
    u.x = a * o.y; u.y = a * o.z; u.z = a * o.w;
    u.w = (lane == 31) ? 0.f : a * nx;
    return u;
}

__global__ void expmap_kernel(const float* __restrict__ P, float* __restrict__ out,
                              const float* __restrict__ cptr) {
    int warp = (blockIdx.x * blockDim.x + threadIdx.x) >> 5;
    int lane = threadIdx.x & 31;
    if (warp >= NN) return;
    float c = cptr[0], sc = sqrtf(c);
    float4 v = ((const float4*)(P + (size_t)warp * HD))[lane];
    float s = warp_sum(v.x * v.x + v.y * v.y + v.z * v.z + v.w * v.w);
    float n = fmaxf(sqrtf(s), 1e-9f);
    float sh = sc * sinhf(n / sc) / n;
    float wprev = __shfl_up_sync(0xffffffffu, v.w, 1);
    float4 o;
    o.x = (lane == 0) ? 0.f : sh * wprev;
    o.y = sh * v.x; o.z = sh * v.y; o.w = sh * v.z;
    float ss = warp_sum(((lane == 0) ? 0.f : o.x * o.x) + o.y * o.y + o.z * o.z + o.w * o.w);
    if (lane == 0) o.x = sqrtf(c + ss);
    ((float4*)(out + (size_t)warp * HD))[lane] = o;
}

__global__ void expmap_u_kernel(const float* __restrict__ P, float* __restrict__ H,
                                float* __restrict__ U, const float* __restrict__ cptr) {
    int warp = (blockIdx.x * blockDim.x + threadIdx.x) >> 5;
    int lane = threadIdx.x & 31;
    if (warp >= NN) return;
    float c = cptr[0], sc = sqrtf(c);
    float4 v = ((const float4*)(P + (size_t)warp * HD))[lane];
    float s = warp_sum(v.x * v.x + v.y * v.y + v.z * v.z + v.w * v.w);
    float n = fmaxf(sqrtf(s), 1e-9f);
    float sh = sc * sinhf(n / sc) / n;
    float wprev = __shfl_up_sync(0xffffffffu, v.w, 1);
    float4 o;
    o.x = (lane == 0) ? 0.f : sh * wprev;
    o.y = sh * v.x; o.z = sh * v.y; o.w = sh * v.z;
    float ss = warp_sum(((lane == 0) ? 0.f : o.x * o.x) + o.y * o.y + o.z * o.z + o.w * o.w);
    float x0 = sqrtf(c + ss);
    if (lane == 0) o.x = x0;
    ((float4*)(H + (size_t)warp * HD))[lane] = o;
    ((float4*)(U + (size_t)warp * HD))[lane] = logmap_quad(o, ss, x0, c, sc, lane);
}

__global__ void agg_combine_kernel(const float* __restrict__ hl, const float* __restrict__ h,
                                   float* __restrict__ U, const float* __restrict__ cptr,
                                   const float* __restrict__ epsp, int l) {
    int warp = (blockIdx.x * blockDim.x + threadIdx.x) >> 5;
    int lane = threadIdx.x & 31;
    if (warp >= NN) return;
    float c = cptr[0], sc = sqrtf(c), ep = epsp[l];
    bool c1 = (sc == 1.f);
    int beg = g_rowptr[warp], end = g_rowptr[warp + 1];
    float4 a = ((const float4*)(hl + (size_t)warp * HD))[lane];
    float ax0 = (lane == 0) ? -a.x : a.x;
    float4 mv = make_float4(0.f, 0.f, 0.f, 0.f);
    int d = (beg < end) ? g_dstidx[beg] : 0;
    for (int e = beg; e < end; e++) {
        int dn = (e + 1 < end) ? g_dstidx[e + 1] : 0;
        float4 b = ((const float4*)(hl + (size_t)d * HD))[lane];
        float4 hv = ((const float4*)(h + (size_t)d * HD))[lane];
        float p = ax0 * b.x + a.y * b.y + a.z * b.z + a.w * b.w;
        p = warp_sum(p);
        float val = fmaxf(-p / c, 1.f + EPSF);
        float att = c1 ? (1.f / (val + sqrtf(val * val - 1.f)))
                       : expf(-sc * acoshf(val));
        mv.x = fmaf(att, hv.x, mv.x);
        mv.y = fmaf(att, hv.y, mv.y);
        mv.z = fmaf(att, hv.z, mv.z);
        mv.w = fmaf(att, hv.w, mv.w);
        d = dn;
    }
    float4 hv = ((const float4*)(h + (size_t)warp * HD))[lane];
    float m0 = __shfl_sync(0xffffffffu, mv.x, 0);
    float pm = warp_sum(((lane == 0) ? 0.f : mv.x * mv.x) + mv.y * mv.y + mv.z * mv.z + mv.w * mv.w);
    float denom = sqrtf(fmaxf(m0 * m0 - pm, 1e-9f));
    float r = sc / denom;
    float axx = r * mv.x, ay = r * mv.y, az = r * mv.z, aw = r * mv.w;
    float ssum = warp_sum(((lane == 0) ? 0.f : axx * axx) + ay * ay + az * az + aw * aw);
    float t = sqrtf(c + ssum);
    float yn_a = fmaxf(sqrtf(ssum), 1e-9f);
    float d1 = sc * acoshf(fmaxf(t / sc, 1.f + EPSF));
    float cA = d1 / yn_a;
    float ph = warp_sum(((lane == 0) ? 0.f : hv.x * hv.x) + hv.y * hv.y + hv.z * hv.z + hv.w * hv.w);
    float hp0 = sqrtf(c + ph);
    float yn_h = fmaxf(sqrtf(ph), 1e-9f);
    float d2 = sc * acoshf(fmaxf(hp0 / sc, 1.f + EPSF));
    float cH = (1.f + ep) * d2 / yn_h;
    float4 vv;
    vv.x = (lane == 0) ? 0.f : cA * axx + cH * hv.x;
    vv.y = cA * ay + cH * hv.y;
    vv.z = cA * az + cH * hv.z;
    vv.w = cA * aw + cH * hv.w;
    float pv = warp_sum(vv.x * vv.x + vv.y * vv.y + vv.z * vv.z + vv.w * vv.w);
    float n = fmaxf(sqrtf(pv), 1e-9f);
    float sh = sc * sinhf(n / sc) / n;
    float4 o;
    o.x = (lane == 0) ? 0.f : sh * vv.x;
    o.y = sh * vv.y; o.z = sh * vv.z; o.w = sh * vv.w;
    float so = warp_sum(((lane == 0) ? 0.f : o.x * o.x) + o.y * o.y + o.z * o.z + o.w * o.w);
    float x0 = sqrtf(c + so);
    if (lane == 0) o.x = x0;
    ((float4*)(U + (size_t)warp * HD))[lane] = logmap_quad(o, so, x0, c, sc, lane);
}

template <bool WRITE_H, bool POOL>
__global__ void mlp_epi_kernel(const float* __restrict__ P, float* __restrict__ H,
                               float* __restrict__ U, const float* __restrict__ cptr,
                               const int* __restrict__ batch, float* __restrict__ out,
                               int loff) {
    int warp = (blockIdx.x * blockDim.x + threadIdx.x) >> 5;
    int lane = threadIdx.x & 31;
    if (warp >= NN) return;
    float c = cptr[0], sc = sqrtf(c);
    float4 v = ((const float4*)(P + (size_t)warp * HD))[lane];
    float s = warp_sum(v.x * v.x + v.y * v.y + v.z * v.z + v.w * v.w);
    float n1 = fmaxf(sqrtf(s), 1e-9f);
    float sh1 = sc * sinhf(n1 / sc) / n1;
    float sx = sh1 * v.x, sy = sh1 * v.y, sz = sh1 * v.z, sw = sh1 * v.w;
    float ssum = warp_sum(sx * sx + sy * sy + sz * sz + sw * sw);
    float x0p = sqrtf(c + ssum);
    float ynp = fmaxf(sqrtf(ssum), 1e-9f);
    float dp = sc * acoshf(fmaxf(x0p / sc, 1.f + EPSF));
    float cf = dp / ynp;
    float tx = tanhf(cf * sx), ty = tanhf(cf * sy), tz = tanhf(cf * sz), tw = tanhf(cf * sw);
    float s2 = warp_sum(tx * tx + ty * ty + tz * tz + tw * tw);
    float n2 = fmaxf(sqrtf(s2), 1e-9f);
    float sh2 = sc * sinhf(n2 / sc) / n2;
    float wprev = __shfl_up_sync(0xffffffffu, tw, 1);
    float x0 = sc * coshf(n2 / sc);
    float4 o;
    o.x = (lane == 0) ? x0 : sh2 * wprev;
    o.y = sh2 * tx; o.z = sh2 * ty; o.w = sh2 * tz;
    if (WRITE_H) ((float4*)(H + (size_t)warp * HD))[lane] = o;
    float sl = warp_sum(((lane == 0) ? 0.f : o.x * o.x) + o.y * o.y + o.z * o.z + o.w * o.w);
    float yn = fmaxf(sqrtf(sl), 1e-9f);
    float d = sc * acoshf(fmaxf(x0 / sc, 1.f + EPSF));
    float a = d / yn;
    float nx = __shfl_down_sync(0xffffffffu, o.x, 1);
    float4 u;
    u.x = a * o.y; u.y = a * o.z; u.z = a * o.w;
    u.w = (lane == 31) ? 0.f : a * nx;
    ((float4*)(U + (size_t)warp * HD))[lane] = u;
    if (POOL) {
        int g = batch[warp];
        red_v4(out + (size_t)g * (2 * HD) + loff + lane * 4,
               (lane == 0) ? 0.f : a * o.x, a * o.y, a * o.z, a * o.w);
    }
}

// ---------------- host launcher ----------------
extern "C" void kernel_launch(void* const* d_in, const int* in_sizes, int n_in,
                              void* d_out, int out_size) {
    (void)in_sizes; (void)n_in; (void)out_size;
    const float* x     = (const float*)d_in[0];
    const float* c     = (const float*)d_in[1];
    const float* w_in  = (const float*)d_in[2];
    const float* att_w = (const float*)d_in[3];
    const float* att_b = (const float*)d_in[4];
    const float* eps   = (const float*)d_in[5];
    const float* mlp_w = (const float*)d_in[6];
    const float* mlp_b = (const float*)d_in[7];
    const int*   ei    = (const int*)d_in[8];
    const int*   batch = (const int*)d_in[9];
    float* out = (float*)d_out;

    float *ph, *pu, *pp, *phl, *pwf, *pwfin;
    int* pcnt;
    cudaGetSymbolAddress((void**)&ph, g_h);
    cudaGetSymbolAddress((void**)&pu, g_u);
    cudaGetSymbolAddress((void**)&pp, g_p);
    cudaGetSymbolAddress((void**)&phl, g_hl);
    cudaGetSymbolAddress((void**)&pwf, g_wf);
    cudaGetSymbolAddress((void**)&pwfin, g_wfin);
    cudaGetSymbolAddress((void**)&pcnt, g_cnt);

    const int NB = (NN + 7) / 8;        // warp-per-node blocks
    const int TB = (NN + 63) / 64;      // tensor GEMM blocks (64 rows each)
    const int SCB = (NN + 255) / 256;   // scan blocks

    zero4_kernel<<<(GG * 2 * HD / 4 + 255) / 256, 256>>>((float4*)out, GG * 2 * HD / 4);
    prep_weights<<<(6 * HD * HD + 255) / 256, 256>>>(att_w, mlp_w);
    prep_win<<<(IN_DIM * HD + 255) / 256, 256>>>(w_in);
    prep_wf<<<(6 * 8 * 16 * 32 + 255) / 256, 256>>>();
    prep_wfin<<<(13 * 16 * 32 + 255) / 256, 256>>>();

    // CSR build (once; reused by both layers)
    zeroi_kernel<<<SCB, 256>>>(pcnt, NN);
    hist_kernel<<<(EE + 255) / 256, 256>>>(ei);
    scan1_kernel<<<SCB, 256>>>();
    scan2_kernel<<<1, 256>>>(SCB);
    scan3_kernel<<<SCB, 256>>>();
    scatter_kernel<<<(EE + 255) / 256, 256>>>(ei);

    // input: h0 = proj(expmap0([0, x @ w_in])), u0 = logmap0(h0)
    gemm_tc_in<<<TB, 256>>>(x, (const uint4*)pwfin, pp);
    expmap_u_kernel<<<NB, 256>>>(pp, ph, pu, c);

    for (int l = 0; l < 2; l++) {
        // attention linear: hl = proj(expmap0(u @ W + b))
        gemm_tc128<true><<<TB, 256>>>(pu, (const uint4*)(pwf + (size_t)l * 8 * 16 * 32 * 4),
                                      att_b + l * DD, pp);
        expmap_kernel<<<NB, 256>>>(pp, phl, c);
        // centroid + GIN combine -> u
        agg_combine_kernel<<<NB, 256>>>(phl, ph, pu, c, eps, l);
        // MLP 0
        gemm_tc128<true><<<TB, 256>>>(pu, (const uint4*)(pwf + (size_t)(2 + l * 2 + 0) * 8 * 16 * 32 * 4),
                                      mlp_b + (l * 2 + 0) * DD, pp);
        mlp_epi_kernel<false, false><<<NB, 256>>>(pp, nullptr, pu, c, nullptr, nullptr, 0);
        // MLP 1 (+ layer output + pooled readout)
        gemm_tc128<true><<<TB, 256>>>(pu, (const uint4*)(pwf + (size_t)(2 + l * 2 + 1) * 8 * 16 * 32 * 4),
                                      mlp_b + (l * 2 + 1) * DD, pp);
        mlp_epi_kernel<true, true><<<NB, 256>>>(pp, ph, pu, c, batch, out, l * HD);
    }
}

// round 12
// speedup vs baseline: 1.0769x; 1.0769x over previous
#include <cuda_runtime.h>
#include <math.h>
#include <stdint.h>

#define NN 50000
#define EE 800000
#define IN_DIM 200
#define HD 128
#define DD 127
#define GG 512
#define EPSF 1e-5f

// ---------------- scratch (device globals; no allocation allowed) ----------------
__device__ float g_h[NN * HD];      // hyperboloid node features
__device__ float g_u[NN * HD];      // logmap0 spatial (slots 0..126, slot127 = 0)
__device__ float g_p[NN * HD];      // GEMM output
__device__ float g_hl[NN * HD];     // attention-linear hyperboloid points
__device__ float g_wt[6 * HD * HD];   // transposed+padded weights (k-major)
__device__ float g_wtin[IN_DIM * HD];
__device__ float g_wf[6 * 8 * 16 * 32 * 4];     // bf16-split fragment weights (K=128 mats)
__device__ float g_wfin[13 * 16 * 32 * 4];      // bf16-split fragment input weights (K=200->208)
__device__ int   g_cnt[NN];
__device__ int   g_rowptr[NN + 1];
__device__ int   g_cur[NN];
__device__ int   g_dstidx[EE];
__device__ int   g_blksum[256];
__device__ int   g_blkoff[256];

__device__ __forceinline__ float warp_sum(float v) {
#pragma unroll
    for (int o = 16; o; o >>= 1) v += __shfl_xor_sync(0xffffffffu, v, o);
    return v;
}

__device__ __forceinline__ void red_v4(float* p, float a, float b, float c, float d) {
    asm volatile("red.global.add.v4.f32 [%0], {%1,%2,%3,%4};"
                 :: "l"(p), "f"(a), "f"(b), "f"(c), "f"(d) : "memory");
}

// m16n8k16 bf16 MMA, fp32 accumulate (A row-major frag, B col-major frag)
__device__ __forceinline__ void mma_bf16(float* d, uint32_t a0, uint32_t a1,
                                         uint32_t a2, uint32_t a3,
                                         uint32_t b0, uint32_t b1) {
    asm("mma.sync.aligned.m16n8k16.row.col.f32.bf16.bf16.f32 "
        "{%0,%1,%2,%3}, {%4,%5,%6,%7}, {%8,%9}, {%0,%1,%2,%3};"
        : "+f"(d[0]), "+f"(d[1]), "+f"(d[2]), "+f"(d[3])
        : "r"(a0), "r"(a1), "r"(a2), "r"(a3), "r"(b0), "r"(b1));
}

// pack two floats into bf16x2 (lower half = x, upper half = y), round-to-nearest
__device__ __forceinline__ uint32_t bf16x2_hi(float x, float y) {
    uint32_t r;
    asm("cvt.rn.bf16x2.f32 %0, %1, %2;" : "=r"(r) : "f"(y), "f"(x));
    return r;
}
// residual pair: lo = f - float(bf16 hi), packed bf16x2
__device__ __forceinline__ uint32_t bf16x2_lo(float x, float y, uint32_t h) {
    float h0 = __uint_as_float(h << 16);
    float h1 = __uint_as_float(h & 0xFFFF0000u);
    return bf16x2_hi(x - h0, y - h1);
}

// ---------------- utility kernels ----------------
__global__ void zero4_kernel(float4* __restrict__ p, int n4) {
    int i = blockIdx.x * blockDim.x + threadIdx.x;
    if (i < n4) p[i] = make_float4(0.f, 0.f, 0.f, 0.f);
}

__global__ void zeroi_kernel(int* __restrict__ p, int n) {
    int i = blockIdx.x * blockDim.x + threadIdx.x;
    if (i < n) p[i] = 0;
}

__global__ void prep_weights(const float* __restrict__ att_w, const float* __restrict__ mlp_w) {
    int idx = blockIdx.x * blockDim.x + threadIdx.x;
    if (idx >= 6 * HD * HD) return;
    int w = idx >> 14;
    int k = (idx >> 7) & 127;
    int j = idx & 127;
    float val = 0.f;
    if (k < DD && j < DD) {
        const float* src = (w < 2) ? (att_w + w * DD * DD) : (mlp_w + (w - 2) * DD * DD);
        val = src[j * DD + k];
    }
    g_wt[idx] = val;
}

__global__ void prep_win(const float* __restrict__ w_in) {
    int idx = blockIdx.x * blockDim.x + threadIdx.x;
    if (idx >= IN_DIM * HD) return;
    int k = idx >> 7;
    int j = idx & 127;
    g_wtin[idx] = (j < DD) ? w_in[k * DD + j] : 0.f;
}

// bf16-split fragment weights: uint4 (b0h, b1h, b0l, b1l) per (mat, k16, tile, lane)
__global__ void prep_wf() {
    int idx = blockIdx.x * blockDim.x + threadIdx.x;
    if (idx >= 6 * 8 * 16 * 32) return;
    int lane = idx & 31;
    int tile = (idx >> 5) & 15;
    int k16 = (idx >> 9) & 7;
    int mat = idx >> 12;
    int gg = lane >> 2, t4 = lane & 3;
    int k0 = k16 * 16 + 2 * t4;
    int n = tile * 8 + gg;
    const float* W = g_wt + mat * HD * HD;
    float w00 = W[k0 * HD + n],       w01 = W[(k0 + 1) * HD + n];
    float w10 = W[(k0 + 8) * HD + n], w11 = W[(k0 + 9) * HD + n];
    uint4 o;
    o.x = bf16x2_hi(w00, w01);
    o.y = bf16x2_hi(w10, w11);
    o.z = bf16x2_lo(w00, w01, o.x);
    o.w = bf16x2_lo(w10, w11, o.y);
    ((uint4*)g_wf)[idx] = o;
}

__global__ void prep_wfin() {
    int idx = blockIdx.x * blockDim.x + threadIdx.x;
    if (idx >= 13 * 16 * 32) return;
    int lane = idx & 31;
    int tile = (idx >> 5) & 15;
    int k16 = idx >> 9;                 // 0..12
    int gg = lane >> 2, t4 = lane & 3;
    int k0 = k16 * 16 + 2 * t4;
    int n = tile * 8 + gg;
    float w00 = (k0 < IN_DIM)     ? g_wtin[k0 * HD + n] : 0.f;
    float w01 = (k0 + 1 < IN_DIM) ? g_wtin[(k0 + 1) * HD + n] : 0.f;
    float w10 = (k0 + 8 < IN_DIM) ? g_wtin[(k0 + 8) * HD + n] : 0.f;
    float w11 = (k0 + 9 < IN_DIM) ? g_wtin[(k0 + 9) * HD + n] : 0.f;
    uint4 o;
    o.x = bf16x2_hi(w00, w01);
    o.y = bf16x2_hi(w10, w11);
    o.z = bf16x2_lo(w00, w01, o.x);
    o.w = bf16x2_lo(w10, w11, o.y);
    ((uint4*)g_wfin)[idx] = o;
}

// ---------------- CSR build ----------------
__global__ void hist_kernel(const int* __restrict__ ei) {
    int e = blockIdx.x * blockDim.x + threadIdx.x;
    if (e < EE) atomicAdd(&g_cnt[ei[e]], 1);
}

__global__ void scan1_kernel() {
    __shared__ int sh[256];
    int t = threadIdx.x;
    int idx = blockIdx.x * 256 + t;
    int v = (idx < NN) ? g_cnt[idx] : 0;
    sh[t] = v;
    __syncthreads();
#pragma unroll
    for (int d = 1; d < 256; d <<= 1) {
        int o = (t >= d) ? sh[t - d] : 0;
        __syncthreads();
        sh[t] += o;
        __syncthreads();
    }
    if (idx < NN) g_rowptr[idx] = sh[t] - v;
    if (t == 255) g_blksum[blockIdx.x] = sh[255];
}

__global__ void scan2_kernel(int nblk) {
    __shared__ int sh[256];
    int t = threadIdx.x;
    int v = (t < nblk) ? g_blksum[t] : 0;
    sh[t] = v;
    __syncthreads();
#pragma unroll
    for (int d = 1; d < 256; d <<= 1) {
        int o = (t >= d) ? sh[t - d] : 0;
        __syncthreads();
        sh[t] += o;
        __syncthreads();
    }
    if (t < nblk) g_blkoff[t] = sh[t] - v;
    if (t == 255) g_rowptr[NN] = sh[255];
}

__global__ void scan3_kernel() {
    int idx = blockIdx.x * 256 + threadIdx.x;
    if (idx >= NN) return;
    int r = g_rowptr[idx] + g_blkoff[blockIdx.x];
    g_rowptr[idx] = r;
    g_cur[idx] = r;
}

__global__ void scatter_kernel(const int* __restrict__ ei) {
    int e = blockIdx.x * blockDim.x + threadIdx.x;
    if (e >= EE) return;
    int s = ei[e];
    int pos = atomicAdd(&g_cur[s], 1);
    g_dstidx[pos] = ei[EE + e];
}

// ---------------- split-bf16 TC GEMM, K=128, m32-per-warp ----------------
// Warp computes a 32-row x 64-col patch: 4 A row-frags reuse each B fragment
// for 2 MMAs (vs 1 in R9) -> B L2 traffic per MAC halved. Block = 8 warps =
// 4 m-warps (m32 each -> 128 rows) x 2 n-warps. Direct A loads (no smem).
template <bool HASBIAS>
__global__ void __launch_bounds__(256) gemm_tc128(const float* __restrict__ U,
                                                  const uint4* __restrict__ WF,
                                                  const float* __restrict__ bias,
                                                  float* __restrict__ P) {
    int tid = threadIdx.x;
    int lane = tid & 31;
    int w = tid >> 5;
    int wm = w & 3;
    int wn = w >> 2;
    int row0 = blockIdx.x * 128;
    int gg = lane >> 2, t4 = lane & 3;
    int ra = row0 + 32 * wm + gg;   // 4 fragment rows: ra, ra+8, ra+16, ra+24
    const float* A0 = U + (size_t)min(ra,      NN - 1) * HD;
    const float* A1 = U + (size_t)min(ra + 8,  NN - 1) * HD;
    const float* A2 = U + (size_t)min(ra + 16, NN - 1) * HD;
    const float* A3 = U + (size_t)min(ra + 24, NN - 1) * HD;

    float acc[8][2][4];   // [n8-tile][m16-half][4]
#pragma unroll
    for (int t = 0; t < 8; t++)
#pragma unroll
        for (int m = 0; m < 2; m++) {
            acc[t][m][0] = 0.f; acc[t][m][1] = 0.f;
            acc[t][m][2] = 0.f; acc[t][m][3] = 0.f;
        }

    for (int k16 = 0; k16 < 8; k16++) {
        int c0 = k16 * 16 + 2 * t4;
        int c1 = c0 + 8;
        float2 f00 = *(const float2*)&A0[c0], f01 = *(const float2*)&A0[c1];
        float2 f10 = *(const float2*)&A1[c0], f11 = *(const float2*)&A1[c1];
        float2 f20 = *(const float2*)&A2[c0], f21 = *(const float2*)&A2[c1];
        float2 f30 = *(const float2*)&A3[c0], f31 = *(const float2*)&A3[c1];
        // m16-half 0: rows ra, ra+8
        uint32_t h0 = bf16x2_hi(f00.x, f00.y), h1 = bf16x2_hi(f10.x, f10.y);
        uint32_t h2 = bf16x2_hi(f01.x, f01.y), h3 = bf16x2_hi(f11.x, f11.y);
        uint32_t l0 = bf16x2_lo(f00.x, f00.y, h0), l1 = bf16x2_lo(f10.x, f10.y, h1);
        uint32_t l2 = bf16x2_lo(f01.x, f01.y, h2), l3 = bf16x2_lo(f11.x, f11.y, h3);
        // m16-half 1: rows ra+16, ra+24
        uint32_t h4 = bf16x2_hi(f20.x, f20.y), h5 = bf16x2_hi(f30.x, f30.y);
        uint32_t h6 = bf16x2_hi(f21.x, f21.y), h7 = bf16x2_hi(f31.x, f31.y);
        uint32_t l4 = bf16x2_lo(f20.x, f20.y, h4), l5 = bf16x2_lo(f30.x, f30.y, h5);
        uint32_t l6 = bf16x2_lo(f21.x, f21.y, h6), l7 = bf16x2_lo(f31.x, f31.y, h7);
        const uint4* wf = WF + ((size_t)k16 * 16 + wn * 8) * 32 + lane;
#pragma unroll
        for (int t = 0; t < 8; t++) {
            uint4 bv = wf[t * 32];   // (b0h, b1h, b0l, b1l) — reused for both m-halves
            mma_bf16(acc[t][0], h0, h1, h2, h3, bv.x, bv.y);
            mma_bf16(acc[t][0], h0, h1, h2, h3, bv.z, bv.w);
            mma_bf16(acc[t][0], l0, l1, l2, l3, bv.x, bv.y);
            mma_bf16(acc[t][1], h4, h5, h6, h7, bv.x, bv.y);
            mma_bf16(acc[t][1], h4, h5, h6, h7, bv.z, bv.w);
            mma_bf16(acc[t][1], l4, l5, l6, l7, bv.x, bv.y);
        }
    }

#pragma unroll
    for (int t = 0; t < 8; t++) {
        int j0 = 64 * wn + 8 * t + 2 * t4;   // even, 0..126
        float b0 = 0.f, b1 = 0.f;
        if (HASBIAS) {
            b0 = bias[j0];
            b1 = (j0 + 1 < DD) ? bias[j0 + 1] : 0.f;
        }
#pragma unroll
        for (int m = 0; m < 2; m++) {
            float d0 = acc[t][m][0] + b0, d1 = acc[t][m][1] + b1;
            float d2 = acc[t][m][2] + b0, d3 = acc[t][m][3] + b1;
            if (j0 + 1 == 127) { d1 = 0.f; d3 = 0.f; }  // padding col
            int r0 = ra + 16 * m;
            int r1 = r0 + 8;
            if (r0 < NN) *(float2*)&P[(size_t)r0 * HD + j0] = make_float2(d0, d1);
            if (r1 < NN) *(float2*)&P[(size_t)r1 * HD + j0] = make_float2(d2, d3);
        }
    }
}

// ---------------- input GEMM K=200 (R9 direct path, runs once; unchanged) ----------------
__global__ void __launch_bounds__(256) gemm_tc_in(const float* __restrict__ U,
                                                  const uint4* __restrict__ WF,
                                                  float* __restrict__ P) {
    constexpr int K = IN_DIM;
    constexpr int K16 = (K + 15) / 16;   // 13
    int tid = threadIdx.x;
    int lane = tid & 31;
    int w = tid >> 5;
    int wm = w & 3;
    int wn = w >> 2;
    int row0 = blockIdx.x * 64;
    int gg = lane >> 2, t4 = lane & 3;
    int ra = row0 + 16 * wm + gg;
    int rb = ra + 8;
    const float* A0 = U + (size_t)min(ra, NN - 1) * K;
    const float* A1 = U + (size_t)min(rb, NN - 1) * K;

    float acc[8][4];
#pragma unroll
    for (int t = 0; t < 8; t++) {
        acc[t][0] = 0.f; acc[t][1] = 0.f; acc[t][2] = 0.f; acc[t][3] = 0.f;
    }

    for (int k16 = 0; k16 < K16; k16++) {
        int kc = k16 * 16;
        int c0 = kc + 2 * t4;
        int c1 = kc + 8 + 2 * t4;
        float2 fa0, fa1, fa2, fa3;
        if (k16 == K16 - 1) {
            fa0.x = (c0 < K) ? A0[c0] : 0.f;     fa0.y = (c0 + 1 < K) ? A0[c0 + 1] : 0.f;
            fa1.x = (c0 < K) ? A1[c0] : 0.f;     fa1.y = (c0 + 1 < K) ? A1[c0 + 1] : 0.f;
            fa2.x = (c1 < K) ? A0[c1] : 0.f;     fa2.y = (c1 + 1 < K) ? A0[c1 + 1] : 0.f;
            fa3.x = (c1 < K) ? A1[c1] : 0.f;     fa3.y = (c1 + 1 < K) ? A1[c1 + 1] : 0.f;
        } else {
            fa0 = *(const float2*)&A0[c0];
            fa1 = *(const float2*)&A1[c0];
            fa2 = *(const float2*)&A0[c1];
            fa3 = *(const float2*)&A1[c1];
        }
        uint32_t h0 = bf16x2_hi(fa0.x, fa0.y), h1 = bf16x2_hi(fa1.x, fa1.y);
        uint32_t h2 = bf16x2_hi(fa2.x, fa2.y), h3 = bf16x2_hi(fa3.x, fa3.y);
        uint32_t l0 = bf16x2_lo(fa0.x, fa0.y, h0), l1 = bf16x2_lo(fa1.x, fa1.y, h1);
        uint32_t l2 = bf16x2_lo(fa2.x, fa2.y, h2), l3 = bf16x2_lo(fa3.x, fa3.y, h3);
        const uint4* wf = WF + ((size_t)k16 * 16 + wn * 8) * 32 + lane;
#pragma unroll
        for (int t = 0; t < 8; t++) {
            uint4 bv = wf[t * 32];
            mma_bf16(acc[t], h0, h1, h2, h3, bv.x, bv.y);
            mma_bf16(acc[t], h0, h1, h2, h3, bv.z, bv.w);
            mma_bf16(acc[t], l0, l1, l2, l3, bv.x, bv.y);
        }
    }

#pragma unroll
    for (int t = 0; t < 8; t++) {
        int j0 = 64 * wn + 8 * t + 2 * t4;
        float d0 = acc[t][0], d1 = acc[t][1];
        float d2 = acc[t][2], d3 = acc[t][3];
        if (j0 + 1 == 127) { d1 = 0.f; d3 = 0.f; }
        if (ra < NN) *(float2*)&P[(size_t)ra * HD + j0] = make_float2(d0, d1);
        if (rb < NN) *(float2*)&P[(size_t)rb * HD + j0] = make_float2(d2, d3);
    }
}

// ---------------- warp-per-node elementwise kernels (unchanged) ----------------

__device__ __forceinline__ float4 logmap_quad(float4 o, float ss, float x0,
                                              float c, float sc, int lane) {
    float yn = fmaxf(sqrtf(ss), 1e-9f);
    float d = sc * acoshf(fmaxf(x0 / sc, 1.f + EPSF));
    float a = d / yn;
    float nx = __shfl_down_sync(0xffffffffu, o.x, 1);
    float4 u;
    u.x = a * o.y; u.y = a * o.z; u.z = a * o.w;
    u.w = (lane == 31) ? 0.f : a * nx;
    return u;
}

__global__ void expmap_kernel(const float* __restrict__ P, float* __restrict__ out,
                              const float* __restrict__ cptr) {
    int warp = (blockIdx.x * blockDim.x + threadIdx.x) >> 5;
    int lane = threadIdx.x & 31;
    if (warp >= NN) return;
    float c = cptr[0], sc = sqrtf(c);
    float4 v = ((const float4*)(P + (size_t)warp * HD))[lane];
    float s = warp_sum(v.x * v.x + v.y * v.y + v.z * v.z + v.w * v.w);
    float n = fmaxf(sqrtf(s), 1e-9f);
    float sh = sc * sinhf(n / sc) / n;
    float wprev = __shfl_up_sync(0xffffffffu, v.w, 1);
    float4 o;
    o.x = (lane == 0) ? 0.f : sh * wprev;
    o.y = sh * v.x; o.z = sh * v.y; o.w = sh * v.z;
    float ss = warp_sum(((lane == 0) ? 0.f : o.x * o.x) + o.y * o.y + o.z * o.z + o.w * o.w);
    if (lane == 0) o.x = sqrtf(c + ss);
    ((float4*)(out + (size_t)warp * HD))[lane] = o;
}

__global__ void expmap_u_kernel(const float* __restrict__ P, float* __restrict__ H,
                                float* __restrict__ U, const float* __restrict__ cptr) {
    int warp = (blockIdx.x * blockDim.x + threadIdx.x) >> 5;
    int lane = threadIdx.x & 31;
    if (warp >= NN) return;
    float c = cptr[0], sc = sqrtf(c);
    float4 v = ((const float4*)(P + (size_t)warp * HD))[lane];
    float s = warp_sum(v.x * v.x + v.y * v.y + v.z * v.z + v.w * v.w);
    float n = fmaxf(sqrtf(s), 1e-9f);
    float sh = sc * sinhf(n / sc) / n;
    float wprev = __shfl_up_sync(0xffffffffu, v.w, 1);
    float4 o;
    o.x = (lane == 0) ? 0.f : sh * wprev;
    o.y = sh * v.x; o.z = sh * v.y; o.w = sh * v.z;
    float ss = warp_sum(((lane == 0) ? 0.f : o.x * o.x) + o.y * o.y + o.z * o.z + o.w * o.w);
    float x0 = sqrtf(c + ss);
    if (lane == 0) o.x = x0;
    ((float4*)(H + (size_t)warp * HD))[lane] = o;
    ((float4*)(U + (size_t)warp * HD))[lane] = logmap_quad(o, ss, x0, c, sc, lane);
}

__global__ void agg_combine_kernel(const float* __restrict__ hl, const float* __restrict__ h,
                                   float* __restrict__ U, const float* __restrict__ cptr,
                                   const float* __restrict__ epsp, int l) {
    int warp = (blockIdx.x * blockDim.x + threadIdx.x) >> 5;
    int lane = threadIdx.x & 31;
    if (warp >= NN) return;
    float c = cptr[0], sc = sqrtf(c), ep = epsp[l];
    bool c1 = (sc == 1.f);
    int beg = g_rowptr[warp], end = g_rowptr[warp + 1];
    float4 a = ((const float4*)(hl + (size_t)warp * HD))[lane];
    float ax0 = (lane == 0) ? -a.x : a.x;
    float4 mv = make_float4(0.f, 0.f, 0.f, 0.f);
    int d = (beg < end) ? g_dstidx[beg] : 0;
    for (int e = beg; e < end; e++) {
        int dn = (e + 1 < end) ? g_dstidx[e + 1] : 0;
        float4 b = ((const float4*)(hl + (size_t)d * HD))[lane];
        float4 hv = ((const float4*)(h + (size_t)d * HD))[lane];
        float p = ax0 * b.x + a.y * b.y + a.z * b.z + a.w * b.w;
        p = warp_sum(p);
        float val = fmaxf(-p / c, 1.f + EPSF);
        float att = c1 ? (1.f / (val + sqrtf(val * val - 1.f)))
                       : expf(-sc * acoshf(val));
        mv.x = fmaf(att, hv.x, mv.x);
        mv.y = fmaf(att, hv.y, mv.y);
        mv.z = fmaf(att, hv.z, mv.z);
        mv.w = fmaf(att, hv.w, mv.w);
        d = dn;
    }
    float4 hv = ((const float4*)(h + (size_t)warp * HD))[lane];
    float m0 = __shfl_sync(0xffffffffu, mv.x, 0);
    float pm = warp_sum(((lane == 0) ? 0.f : mv.x * mv.x) + mv.y * mv.y + mv.z * mv.z + mv.w * mv.w);
    float denom = sqrtf(fmaxf(m0 * m0 - pm, 1e-9f));
    float r = sc / denom;
    float axx = r * mv.x, ay = r * mv.y, az = r * mv.z, aw = r * mv.w;
    float ssum = warp_sum(((lane == 0) ? 0.f : axx * axx) + ay * ay + az * az + aw * aw);
    float t = sqrtf(c + ssum);
    float yn_a = fmaxf(sqrtf(ssum), 1e-9f);
    float d1 = sc * acoshf(fmaxf(t / sc, 1.f + EPSF));
    float cA = d1 / yn_a;
    float ph = warp_sum(((lane == 0) ? 0.f : hv.x * hv.x) + hv.y * hv.y + hv.z * hv.z + hv.w * hv.w);
    float hp0 = sqrtf(c + ph);
    float yn_h = fmaxf(sqrtf(ph), 1e-9f);
    float d2 = sc * acoshf(fmaxf(hp0 / sc, 1.f + EPSF));
    float cH = (1.f + ep) * d2 / yn_h;
    float4 vv;
    vv.x = (lane == 0) ? 0.f : cA * axx + cH * hv.x;
    vv.y = cA * ay + cH * hv.y;
    vv.z = cA * az + cH * hv.z;
    vv.w = cA * aw + cH * hv.w;
    float pv = warp_sum(vv.x * vv.x + vv.y * vv.y + vv.z * vv.z + vv.w * vv.w);
    float n = fmaxf(sqrtf(pv), 1e-9f);
    float sh = sc * sinhf(n / sc) / n;
    float4 o;
    o.x = (lane == 0) ? 0.f : sh * vv.x;
    o.y = sh * vv.y; o.z = sh * vv.z; o.w = sh * vv.w;
    float so = warp_sum(((lane == 0) ? 0.f : o.x * o.x) + o.y * o.y + o.z * o.z + o.w * o.w);
    float x0 = sqrtf(c + so);
    if (lane == 0) o.x = x0;
    ((float4*)(U + (size_t)warp * HD))[lane] = logmap_quad(o, so, x0, c, sc, lane);
}

template <bool WRITE_H, bool POOL>
__global__ void mlp_epi_kernel(const float* __restrict__ P, float* __restrict__ H,
                               float* __restrict__ U, const float* __restrict__ cptr,
                               const int* __restrict__ batch, float* __restrict__ out,
                               int loff) {
    int warp = (blockIdx.x * blockDim.x + threadIdx.x) >> 5;
    int lane = threadIdx.x & 31;
    if (warp >= NN) return;
    float c = cptr[0], sc = sqrtf(c);
    float4 v = ((const float4*)(P + (size_t)warp * HD))[lane];
    float s = warp_sum(v.x * v.x + v.y * v.y + v.z * v.z + v.w * v.w);
    float n1 = fmaxf(sqrtf(s), 1e-9f);
    float sh1 = sc * sinhf(n1 / sc) / n1;
    float sx = sh1 * v.x, sy = sh1 * v.y, sz = sh1 * v.z, sw = sh1 * v.w;
    float ssum = warp_sum(sx * sx + sy * sy + sz * sz + sw * sw);
    float x0p = sqrtf(c + ssum);
    float ynp = fmaxf(sqrtf(ssum), 1e-9f);
    float dp = sc * acoshf(fmaxf(x0p / sc, 1.f + EPSF));
    float cf = dp / ynp;
    float tx = tanhf(cf * sx), ty = tanhf(cf * sy), tz = tanhf(cf * sz), tw = tanhf(cf * sw);
    float s2 = warp_sum(tx * tx + ty * ty + tz * tz + tw * tw);
    float n2 = fmaxf(sqrtf(s2), 1e-9f);
    float sh2 = sc * sinhf(n2 / sc) / n2;
    float wprev = __shfl_up_sync(0xffffffffu, tw, 1);
    float x0 = sc * coshf(n2 / sc);
    float4 o;
    o.x = (lane == 0) ? x0 : sh2 * wprev;
    o.y = sh2 * tx; o.z = sh2 * ty; o.w = sh2 * tz;
    if (WRITE_H) ((float4*)(H + (size_t)warp * HD))[lane] = o;
    float sl = warp_sum(((lane == 0) ? 0.f : o.x * o.x) + o.y * o.y + o.z * o.z + o.w * o.w);
    float yn = fmaxf(sqrtf(sl), 1e-9f);
    float d = sc * acoshf(fmaxf(x0 / sc, 1.f + EPSF));
    float a = d / yn;
    float nx = __shfl_down_sync(0xffffffffu, o.x, 1);
    float4 u;
    u.x = a * o.y; u.y = a * o.z; u.z = a * o.w;
    u.w = (lane == 31) ? 0.f : a * nx;
    ((float4*)(U + (size_t)warp * HD))[lane] = u;
    if (POOL) {
        int g = batch[warp];
        red_v4(out + (size_t)g * (2 * HD) + loff + lane * 4,
               (lane == 0) ? 0.f : a * o.x, a * o.y, a * o.z, a * o.w);
    }
}

// ---------------- host launcher ----------------
extern "C" void kernel_launch(void* const* d_in, const int* in_sizes, int n_in,
                              void* d_out, int out_size) {
    (void)in_sizes; (void)n_in; (void)out_size;
    const float* x     = (const float*)d_in[0];
    const float* c     = (const float*)d_in[1];
    const float* w_in  = (const float*)d_in[2];
    const float* att_w = (const float*)d_in[3];
    const float* att_b = (const float*)d_in[4];
    const float* eps   = (const float*)d_in[5];
    const float* mlp_w = (const float*)d_in[6];
    const float* mlp_b = (const float*)d_in[7];
    const int*   ei    = (const int*)d_in[8];
    const int*   batch = (const int*)d_in[9];
    float* out = (float*)d_out;

    float *ph, *pu, *pp, *phl, *pwf, *pwfin;
    int* pcnt;
    cudaGetSymbolAddress((void**)&ph, g_h);
    cudaGetSymbolAddress((void**)&pu, g_u);
    cudaGetSymbolAddress((void**)&pp, g_p);
    cudaGetSymbolAddress((void**)&phl, g_hl);
    cudaGetSymbolAddress((void**)&pwf, g_wf);
    cudaGetSymbolAddress((void**)&pwfin, g_wfin);
    cudaGetSymbolAddress((void**)&pcnt, g_cnt);

    const int NB = (NN + 7) / 8;         // warp-per-node blocks
    const int TB64 = (NN + 63) / 64;     // input GEMM blocks (64 rows)
    const int TB128 = (NN + 127) / 128;  // m32 GEMM blocks (128 rows)
    const int SCB = (NN + 255) / 256;    // scan blocks

    zero4_kernel<<<(GG * 2 * HD / 4 + 255) / 256, 256>>>((float4*)out, GG * 2 * HD / 4);
    prep_weights<<<(6 * HD * HD + 255) / 256, 256>>>(att_w, mlp_w);
    prep_win<<<(IN_DIM * HD + 255) / 256, 256>>>(w_in);
    prep_wf<<<(6 * 8 * 16 * 32 + 255) / 256, 256>>>();
    prep_wfin<<<(13 * 16 * 32 + 255) / 256, 256>>>();

    // CSR build (once; reused by both layers)
    zeroi_kernel<<<SCB, 256>>>(pcnt, NN);
    hist_kernel<<<(EE + 255) / 256, 256>>>(ei);
    scan1_kernel<<<SCB, 256>>>();
    scan2_kernel<<<1, 256>>>(SCB);
    scan3_kernel<<<SCB, 256>>>();
    scatter_kernel<<<(EE + 255) / 256, 256>>>(ei);

    // input: h0 = proj(expmap0([0, x @ w_in])), u0 = logmap0(h0)
    gemm_tc_in<<<TB64, 256>>>(x, (const uint4*)pwfin, pp);
    expmap_u_kernel<<<NB, 256>>>(pp, ph, pu, c);

    for (int l = 0; l < 2; l++) {
        // attention linear: hl = proj(expmap0(u @ W + b))
        gemm_tc128<true><<<TB128, 256>>>(pu, (const uint4*)(pwf + (size_t)l * 8 * 16 * 32 * 4),
                                         att_b + l * DD, pp);
        expmap_kernel<<<NB, 256>>>(pp, phl, c);
        // centroid + GIN combine -> u
        agg_combine_kernel<<<NB, 256>>>(phl, ph, pu, c, eps, l);
        // MLP 0
        gemm_tc128<true><<<TB128, 256>>>(pu, (const uint4*)(pwf + (size_t)(2 + l * 2 + 0) * 8 * 16 * 32 * 4),
                                         mlp_b + (l * 2 + 0) * DD, pp);
        mlp_epi_kernel<false, false><<<NB, 256>>>(pp, nullptr, pu, c, nullptr, nullptr, 0);
        // MLP 1 (+ layer output + pooled readout)
        gemm_tc128<true><<<TB128, 256>>>(pu, (const uint4*)(pwf + (size_t)(2 + l * 2 + 1) * 8 * 16 * 32 * 4),
                                         mlp_b + (l * 2 + 1) * DD, pp);
        mlp_epi_kernel<true, true><<<NB, 256>>>(pp, ph, pu, c, batch, out, l * HD);
    }
}

// round 13
// speedup vs baseline: 1.0876x; 1.0099x over previous
#include <cuda_runtime.h>
#include <math.h>
#include <stdint.h>

#define NN 50000
#define EE 800000
#define IN_DIM 200
#define HD 128
#define DD 127
#define GG 512
#define EPSF 1e-5f

// ---------------- scratch (device globals; no allocation allowed) ----------------
__device__ float g_h[NN * HD];      // hyperboloid node features
__device__ float g_u[NN * HD];      // logmap0 spatial (slots 0..126, slot127 = 0)
__device__ float g_p[NN * HD];      // GEMM output
__device__ float g_hl[NN * HD];     // attention-linear hyperboloid points
__device__ float g_wt[6 * HD * HD];   // transposed+padded weights (k-major)
__device__ float g_wtin[IN_DIM * HD];
__device__ float g_wf[6 * 8 * 16 * 32 * 4];     // bf16-split fragment weights (K=128 mats)
__device__ float g_wfin[13 * 16 * 32 * 4];      // bf16-split fragment input weights (K=200->208)
__device__ int   g_cnt[NN];
__device__ int   g_rowptr[NN + 1];
__device__ int   g_cur[NN];
__device__ int   g_dstidx[EE];
__device__ int   g_blksum[256];
__device__ int   g_blkoff[256];

__device__ __forceinline__ float warp_sum(float v) {
#pragma unroll
    for (int o = 16; o; o >>= 1) v += __shfl_xor_sync(0xffffffffu, v, o);
    return v;
}

__device__ __forceinline__ void red_v4(float* p, float a, float b, float c, float d) {
    asm volatile("red.global.add.v4.f32 [%0], {%1,%2,%3,%4};"
                 :: "l"(p), "f"(a), "f"(b), "f"(c), "f"(d) : "memory");
}

// m16n8k16 bf16 MMA, fp32 accumulate (A row-major frag, B col-major frag)
__device__ __forceinline__ void mma_bf16(float* d, uint32_t a0, uint32_t a1,
                                         uint32_t a2, uint32_t a3,
                                         uint32_t b0, uint32_t b1) {
    asm("mma.sync.aligned.m16n8k16.row.col.f32.bf16.bf16.f32 "
        "{%0,%1,%2,%3}, {%4,%5,%6,%7}, {%8,%9}, {%0,%1,%2,%3};"
        : "+f"(d[0]), "+f"(d[1]), "+f"(d[2]), "+f"(d[3])
        : "r"(a0), "r"(a1), "r"(a2), "r"(a3), "r"(b0), "r"(b1));
}

// pack two floats into bf16x2 (lower half = x, upper half = y), round-to-nearest
__device__ __forceinline__ uint32_t bf16x2_hi(float x, float y) {
    uint32_t r;
    asm("cvt.rn.bf16x2.f32 %0, %1, %2;" : "=r"(r) : "f"(y), "f"(x));
    return r;
}
// residual pair: lo = f - float(bf16 hi), packed bf16x2
__device__ __forceinline__ uint32_t bf16x2_lo(float x, float y, uint32_t h) {
    float h0 = __uint_as_float(h << 16);
    float h1 = __uint_as_float(h & 0xFFFF0000u);
    return bf16x2_hi(x - h0, y - h1);
}

// ---------------- utility kernels ----------------
__global__ void zero4_kernel(float4* __restrict__ p, int n4) {
    int i = blockIdx.x * blockDim.x + threadIdx.x;
    if (i < n4) p[i] = make_float4(0.f, 0.f, 0.f, 0.f);
}

__global__ void zeroi_kernel(int* __restrict__ p, int n) {
    int i = blockIdx.x * blockDim.x + threadIdx.x;
    if (i < n) p[i] = 0;
}

__global__ void prep_weights(const float* __restrict__ att_w, const float* __restrict__ mlp_w) {
    int idx = blockIdx.x * blockDim.x + threadIdx.x;
    if (idx >= 6 * HD * HD) return;
    int w = idx >> 14;
    int k = (idx >> 7) & 127;
    int j = idx & 127;
    float val = 0.f;
    if (k < DD && j < DD) {
        const float* src = (w < 2) ? (att_w + w * DD * DD) : (mlp_w + (w - 2) * DD * DD);
        val = src[j * DD + k];
    }
    g_wt[idx] = val;
}

__global__ void prep_win(const float* __restrict__ w_in) {
    int idx = blockIdx.x * blockDim.x + threadIdx.x;
    if (idx >= IN_DIM * HD) return;
    int k = idx >> 7;
    int j = idx & 127;
    g_wtin[idx] = (j < DD) ? w_in[k * DD + j] : 0.f;
}

// bf16-split fragment weights: uint4 (b0h, b1h, b0l, b1l) per (mat, k16, tile, lane)
__global__ void prep_wf() {
    int idx = blockIdx.x * blockDim.x + threadIdx.x;
    if (idx >= 6 * 8 * 16 * 32) return;
    int lane = idx & 31;
    int tile = (idx >> 5) & 15;
    int k16 = (idx >> 9) & 7;
    int mat = idx >> 12;
    int gg = lane >> 2, t4 = lane & 3;
    int k0 = k16 * 16 + 2 * t4;
    int n = tile * 8 + gg;
    const float* W = g_wt + mat * HD * HD;
    float w00 = W[k0 * HD + n],       w01 = W[(k0 + 1) * HD + n];
    float w10 = W[(k0 + 8) * HD + n], w11 = W[(k0 + 9) * HD + n];
    uint4 o;
    o.x = bf16x2_hi(w00, w01);
    o.y = bf16x2_hi(w10, w11);
    o.z = bf16x2_lo(w00, w01, o.x);
    o.w = bf16x2_lo(w10, w11, o.y);
    ((uint4*)g_wf)[idx] = o;
}

__global__ void prep_wfin() {
    int idx = blockIdx.x * blockDim.x + threadIdx.x;
    if (idx >= 13 * 16 * 32) return;
    int lane = idx & 31;
    int tile = (idx >> 5) & 15;
    int k16 = idx >> 9;                 // 0..12
    int gg = lane >> 2, t4 = lane & 3;
    int k0 = k16 * 16 + 2 * t4;
    int n = tile * 8 + gg;
    float w00 = (k0 < IN_DIM)     ? g_wtin[k0 * HD + n] : 0.f;
    float w01 = (k0 + 1 < IN_DIM) ? g_wtin[(k0 + 1) * HD + n] : 0.f;
    float w10 = (k0 + 8 < IN_DIM) ? g_wtin[(k0 + 8) * HD + n] : 0.f;
    float w11 = (k0 + 9 < IN_DIM) ? g_wtin[(k0 + 9) * HD + n] : 0.f;
    uint4 o;
    o.x = bf16x2_hi(w00, w01);
    o.y = bf16x2_hi(w10, w11);
    o.z = bf16x2_lo(w00, w01, o.x);
    o.w = bf16x2_lo(w10, w11, o.y);
    ((uint4*)g_wfin)[idx] = o;
}

// ---------------- CSR build ----------------
__global__ void hist_kernel(const int* __restrict__ ei) {
    int e = blockIdx.x * blockDim.x + threadIdx.x;
    if (e < EE) atomicAdd(&g_cnt[ei[e]], 1);
}

__global__ void scan1_kernel() {
    __shared__ int sh[256];
    int t = threadIdx.x;
    int idx = blockIdx.x * 256 + t;
    int v = (idx < NN) ? g_cnt[idx] : 0;
    sh[t] = v;
    __syncthreads();
#pragma unroll
    for (int d = 1; d < 256; d <<= 1) {
        int o = (t >= d) ? sh[t - d] : 0;
        __syncthreads();
        sh[t] += o;
        __syncthreads();
    }
    if (idx < NN) g_rowptr[idx] = sh[t] - v;
    if (t == 255) g_blksum[blockIdx.x] = sh[255];
}

__global__ void scan2_kernel(int nblk) {
    __shared__ int sh[256];
    int t = threadIdx.x;
    int v = (t < nblk) ? g_blksum[t] : 0;
    sh[t] = v;
    __syncthreads();
#pragma unroll
    for (int d = 1; d < 256; d <<= 1) {
        int o = (t >= d) ? sh[t - d] : 0;
        __syncthreads();
        sh[t] += o;
        __syncthreads();
    }
    if (t < nblk) g_blkoff[t] = sh[t] - v;
    if (t == 255) g_rowptr[NN] = sh[255];
}

__global__ void scan3_kernel() {
    int idx = blockIdx.x * 256 + threadIdx.x;
    if (idx >= NN) return;
    int r = g_rowptr[idx] + g_blkoff[blockIdx.x];
    g_rowptr[idx] = r;
    g_cur[idx] = r;
}

__global__ void scatter_kernel(const int* __restrict__ ei) {
    int e = blockIdx.x * blockDim.x + threadIdx.x;
    if (e >= EE) return;
    int s = ei[e];
    int pos = atomicAdd(&g_cur[s], 1);
    g_dstidx[pos] = ei[EE + e];
}

// ---------------- split-bf16 TC GEMM, K=128, m32-per-warp (R11 winner) ----------------
template <bool HASBIAS>
__global__ void __launch_bounds__(256) gemm_tc128(const float* __restrict__ U,
                                                  const uint4* __restrict__ WF,
                                                  const float* __restrict__ bias,
                                                  float* __restrict__ P) {
    int tid = threadIdx.x;
    int lane = tid & 31;
    int w = tid >> 5;
    int wm = w & 3;
    int wn = w >> 2;
    int row0 = blockIdx.x * 128;
    int gg = lane >> 2, t4 = lane & 3;
    int ra = row0 + 32 * wm + gg;   // 4 fragment rows: ra, ra+8, ra+16, ra+24
    const float* A0 = U + (size_t)min(ra,      NN - 1) * HD;
    const float* A1 = U + (size_t)min(ra + 8,  NN - 1) * HD;
    const float* A2 = U + (size_t)min(ra + 16, NN - 1) * HD;
    const float* A3 = U + (size_t)min(ra + 24, NN - 1) * HD;

    float acc[8][2][4];   // [n8-tile][m16-half][4]
#pragma unroll
    for (int t = 0; t < 8; t++)
#pragma unroll
        for (int m = 0; m < 2; m++) {
            acc[t][m][0] = 0.f; acc[t][m][1] = 0.f;
            acc[t][m][2] = 0.f; acc[t][m][3] = 0.f;
        }

    for (int k16 = 0; k16 < 8; k16++) {
        int c0 = k16 * 16 + 2 * t4;
        int c1 = c0 + 8;
        float2 f00 = *(const float2*)&A0[c0], f01 = *(const float2*)&A0[c1];
        float2 f10 = *(const float2*)&A1[c0], f11 = *(const float2*)&A1[c1];
        float2 f20 = *(const float2*)&A2[c0], f21 = *(const float2*)&A2[c1];
        float2 f30 = *(const float2*)&A3[c0], f31 = *(const float2*)&A3[c1];
        uint32_t h0 = bf16x2_hi(f00.x, f00.y), h1 = bf16x2_hi(f10.x, f10.y);
        uint32_t h2 = bf16x2_hi(f01.x, f01.y), h3 = bf16x2_hi(f11.x, f11.y);
        uint32_t l0 = bf16x2_lo(f00.x, f00.y, h0), l1 = bf16x2_lo(f10.x, f10.y, h1);
        uint32_t l2 = bf16x2_lo(f01.x, f01.y, h2), l3 = bf16x2_lo(f11.x, f11.y, h3);
        uint32_t h4 = bf16x2_hi(f20.x, f20.y), h5 = bf16x2_hi(f30.x, f30.y);
        uint32_t h6 = bf16x2_hi(f21.x, f21.y), h7 = bf16x2_hi(f31.x, f31.y);
        uint32_t l4 = bf16x2_lo(f20.x, f20.y, h4), l5 = bf16x2_lo(f30.x, f30.y, h5);
        uint32_t l6 = bf16x2_lo(f21.x, f21.y, h6), l7 = bf16x2_lo(f31.x, f31.y, h7);
        const uint4* wf = WF + ((size_t)k16 * 16 + wn * 8) * 32 + lane;
#pragma unroll
        for (int t = 0; t < 8; t++) {
            uint4 bv = wf[t * 32];   // (b0h, b1h, b0l, b1l) — reused for both m-halves
            mma_bf16(acc[t][0], h0, h1, h2, h3, bv.x, bv.y);
            mma_bf16(acc[t][0], h0, h1, h2, h3, bv.z, bv.w);
            mma_bf16(acc[t][0], l0, l1, l2, l3, bv.x, bv.y);
            mma_bf16(acc[t][1], h4, h5, h6, h7, bv.x, bv.y);
            mma_bf16(acc[t][1], h4, h5, h6, h7, bv.z, bv.w);
            mma_bf16(acc[t][1], l4, l5, l6, l7, bv.x, bv.y);
        }
    }

#pragma unroll
    for (int t = 0; t < 8; t++) {
        int j0 = 64 * wn + 8 * t + 2 * t4;   // even, 0..126
        float b0 = 0.f, b1 = 0.f;
        if (HASBIAS) {
            b0 = bias[j0];
            b1 = (j0 + 1 < DD) ? bias[j0 + 1] : 0.f;
        }
#pragma unroll
        for (int m = 0; m < 2; m++) {
            float d0 = acc[t][m][0] + b0, d1 = acc[t][m][1] + b1;
            float d2 = acc[t][m][2] + b0, d3 = acc[t][m][3] + b1;
            if (j0 + 1 == 127) { d1 = 0.f; d3 = 0.f; }  // padding col
            int r0 = ra + 16 * m;
            int r1 = r0 + 8;
            if (r0 < NN) *(float2*)&P[(size_t)r0 * HD + j0] = make_float2(d0, d1);
            if (r1 < NN) *(float2*)&P[(size_t)r1 * HD + j0] = make_float2(d2, d3);
        }
    }
}

// ---------------- input GEMM K=200 (direct path, runs once; unchanged) ----------------
__global__ void __launch_bounds__(256) gemm_tc_in(const float* __restrict__ U,
                                                  const uint4* __restrict__ WF,
                                                  float* __restrict__ P) {
    constexpr int K = IN_DIM;
    constexpr int K16 = (K + 15) / 16;   // 13
    int tid = threadIdx.x;
    int lane = tid & 31;
    int w = tid >> 5;
    int wm = w & 3;
    int wn = w >> 2;
    int row0 = blockIdx.x * 64;
    int gg = lane >> 2, t4 = lane & 3;
    int ra = row0 + 16 * wm + gg;
    int rb = ra + 8;
    const float* A0 = U + (size_t)min(ra, NN - 1) * K;
    const float* A1 = U + (size_t)min(rb, NN - 1) * K;

    float acc[8][4];
#pragma unroll
    for (int t = 0; t < 8; t++) {
        acc[t][0] = 0.f; acc[t][1] = 0.f; acc[t][2] = 0.f; acc[t][3] = 0.f;
    }

    for (int k16 = 0; k16 < K16; k16++) {
        int kc = k16 * 16;
        int c0 = kc + 2 * t4;
        int c1 = kc + 8 + 2 * t4;
        float2 fa0, fa1, fa2, fa3;
        if (k16 == K16 - 1) {
            fa0.x = (c0 < K) ? A0[c0] : 0.f;     fa0.y = (c0 + 1 < K) ? A0[c0 + 1] : 0.f;
            fa1.x = (c0 < K) ? A1[c0] : 0.f;     fa1.y = (c0 + 1 < K) ? A1[c0 + 1] : 0.f;
            fa2.x = (c1 < K) ? A0[c1] : 0.f;     fa2.y = (c1 + 1 < K) ? A0[c1 + 1] : 0.f;
            fa3.x = (c1 < K) ? A1[c1] : 0.f;     fa3.y = (c1 + 1 < K) ? A1[c1 + 1] : 0.f;
        } else {
            fa0 = *(const float2*)&A0[c0];
            fa1 = *(const float2*)&A1[c0];
            fa2 = *(const float2*)&A0[c1];
            fa3 = *(const float2*)&A1[c1];
        }
        uint32_t h0 = bf16x2_hi(fa0.x, fa0.y), h1 = bf16x2_hi(fa1.x, fa1.y);
        uint32_t h2 = bf16x2_hi(fa2.x, fa2.y), h3 = bf16x2_hi(fa3.x, fa3.y);
        uint32_t l0 = bf16x2_lo(fa0.x, fa0.y, h0), l1 = bf16x2_lo(fa1.x, fa1.y, h1);
        uint32_t l2 = bf16x2_lo(fa2.x, fa2.y, h2), l3 = bf16x2_lo(fa3.x, fa3.y, h3);
        const uint4* wf = WF + ((size_t)k16 * 16 + wn * 8) * 32 + lane;
#pragma unroll
        for (int t = 0; t < 8; t++) {
            uint4 bv = wf[t * 32];
            mma_bf16(acc[t], h0, h1, h2, h3, bv.x, bv.y);
            mma_bf16(acc[t], h0, h1, h2, h3, bv.z, bv.w);
            mma_bf16(acc[t], l0, l1, l2, l3, bv.x, bv.y);
        }
    }

#pragma unroll
    for (int t = 0; t < 8; t++) {
        int j0 = 64 * wn + 8 * t + 2 * t4;
        float d0 = acc[t][0], d1 = acc[t][1];
        float d2 = acc[t][2], d3 = acc[t][3];
        if (j0 + 1 == 127) { d1 = 0.f; d3 = 0.f; }
        if (ra < NN) *(float2*)&P[(size_t)ra * HD + j0] = make_float2(d0, d1);
        if (rb < NN) *(float2*)&P[(size_t)rb * HD + j0] = make_float2(d2, d3);
    }
}

// ---------------- warp-per-node elementwise kernels ----------------

__device__ __forceinline__ float4 logmap_quad(float4 o, float ss, float x0,
                                              float c, float sc, int lane) {
    float yn = fmaxf(sqrtf(ss), 1e-9f);
    float d = sc * acoshf(fmaxf(x0 / sc, 1.f + EPSF));
    float a = d / yn;
    float nx = __shfl_down_sync(0xffffffffu, o.x, 1);
    float4 u;
    u.x = a * o.y; u.y = a * o.z; u.z = a * o.w;
    u.w = (lane == 31) ? 0.f : a * nx;
    return u;
}

__global__ void expmap_kernel(const float* __restrict__ P, float* __restrict__ out,
                              const float* __restrict__ cptr) {
    int warp = (blockIdx.x * blockDim.x + threadIdx.x) >> 5;
    int lane = threadIdx.x & 31;
    if (warp >= NN) return;
    float c = cptr[0], sc = sqrtf(c);
    float4 v = ((const float4*)(P + (size_t)warp * HD))[lane];
    float s = warp_sum(v.x * v.x + v.y * v.y + v.z * v.z + v.w * v.w);
    float n = fmaxf(sqrtf(s), 1e-9f);
    float sh = sc * sinhf(n / sc) / n;
    float wprev = __shfl_up_sync(0xffffffffu, v.w, 1);
    float4 o;
    o.x = (lane == 0) ? 0.f : sh * wprev;
    o.y = sh * v.x; o.z = sh * v.y; o.w = sh * v.z;
    float ss = warp_sum(((lane == 0) ? 0.f : o.x * o.x) + o.y * o.y + o.z * o.z + o.w * o.w);
    if (lane == 0) o.x = sqrtf(c + ss);
    ((float4*)(out + (size_t)warp * HD))[lane] = o;
}

__global__ void expmap_u_kernel(const float* __restrict__ P, float* __restrict__ H,
                                float* __restrict__ U, const float* __restrict__ cptr) {
    int warp = (blockIdx.x * blockDim.x + threadIdx.x) >> 5;
    int lane = threadIdx.x & 31;
    if (warp >= NN) return;
    float c = cptr[0], sc = sqrtf(c);
    float4 v = ((const float4*)(P + (size_t)warp * HD))[lane];
    float s = warp_sum(v.x * v.x + v.y * v.y + v.z * v.z + v.w * v.w);
    float n = fmaxf(sqrtf(s), 1e-9f);
    float sh = sc * sinhf(n / sc) / n;
    float wprev = __shfl_up_sync(0xffffffffu, v.w, 1);
    float4 o;
    o.x = (lane == 0) ? 0.f : sh * wprev;
    o.y = sh * v.x; o.z = sh * v.y; o.w = sh * v.z;
    float ss = warp_sum(((lane == 0) ? 0.f : o.x * o.x) + o.y * o.y + o.z * o.z + o.w * o.w);
    float x0 = sqrtf(c + ss);
    if (lane == 0) o.x = x0;
    ((float4*)(H + (size_t)warp * HD))[lane] = o;
    ((float4*)(U + (size_t)warp * HD))[lane] = logmap_quad(o, ss, x0, c, sc, lane);
}

// warp per node: CSR centroid (2-edge ILP) + GIN combine; emits u = logmap0(result).
__global__ void agg_combine_kernel(const float* __restrict__ hl, const float* __restrict__ h,
                                   float* __restrict__ U, const float* __restrict__ cptr,
                                   const float* __restrict__ epsp, int l) {
    int warp = (blockIdx.x * blockDim.x + threadIdx.x) >> 5;
    int lane = threadIdx.x & 31;
    if (warp >= NN) return;
    float c = cptr[0], sc = sqrtf(c), ep = epsp[l];
    bool c1 = (sc == 1.f);
    int beg = g_rowptr[warp], end = g_rowptr[warp + 1];
    float4 a = ((const float4*)(hl + (size_t)warp * HD))[lane];
    float ax0 = (lane == 0) ? -a.x : a.x;   // hoisted Lorentz sign
    float4 mv = make_float4(0.f, 0.f, 0.f, 0.f);

    int e = beg;
    // 2-edge ILP: two independent load+reduce chains interleaved; FMA accumulation
    // applied in original edge order -> bitwise identical to the sequential loop.
    for (; e + 1 < end; e += 2) {
        int d0i = g_dstidx[e];
        int d1i = g_dstidx[e + 1];
        const float4* b0p = (const float4*)(hl + (size_t)d0i * HD);
        const float4* b1p = (const float4*)(hl + (size_t)d1i * HD);
        const float4* h0p = (const float4*)(h + (size_t)d0i * HD);
        const float4* h1p = (const float4*)(h + (size_t)d1i * HD);
        float4 b0 = b0p[lane];
        float4 b1 = b1p[lane];
        float4 hv0 = h0p[lane];
        float4 hv1 = h1p[lane];
        float p0 = ax0 * b0.x + a.y * b0.y + a.z * b0.z + a.w * b0.w;
        float p1 = ax0 * b1.x + a.y * b1.y + a.z * b1.z + a.w * b1.w;
#pragma unroll
        for (int o = 16; o; o >>= 1) {
            p0 += __shfl_xor_sync(0xffffffffu, p0, o);
            p1 += __shfl_xor_sync(0xffffffffu, p1, o);
        }
        float val0 = fmaxf(-p0 / c, 1.f + EPSF);
        float val1 = fmaxf(-p1 / c, 1.f + EPSF);
        float att0 = c1 ? (1.f / (val0 + sqrtf(val0 * val0 - 1.f)))
                        : expf(-sc * acoshf(val0));
        float att1 = c1 ? (1.f / (val1 + sqrtf(val1 * val1 - 1.f)))
                        : expf(-sc * acoshf(val1));
        mv.x = fmaf(att0, hv0.x, mv.x);
        mv.y = fmaf(att0, hv0.y, mv.y);
        mv.z = fmaf(att0, hv0.z, mv.z);
        mv.w = fmaf(att0, hv0.w, mv.w);
        mv.x = fmaf(att1, hv1.x, mv.x);
        mv.y = fmaf(att1, hv1.y, mv.y);
        mv.z = fmaf(att1, hv1.z, mv.z);
        mv.w = fmaf(att1, hv1.w, mv.w);
    }
    if (e < end) {   // odd tail
        int di = g_dstidx[e];
        float4 b = ((const float4*)(hl + (size_t)di * HD))[lane];
        float4 hv = ((const float4*)(h + (size_t)di * HD))[lane];
        float p = ax0 * b.x + a.y * b.y + a.z * b.z + a.w * b.w;
        p = warp_sum(p);
        float val = fmaxf(-p / c, 1.f + EPSF);
        float att = c1 ? (1.f / (val + sqrtf(val * val - 1.f)))
                       : expf(-sc * acoshf(val));
        mv.x = fmaf(att, hv.x, mv.x);
        mv.y = fmaf(att, hv.y, mv.y);
        mv.z = fmaf(att, hv.z, mv.z);
        mv.w = fmaf(att, hv.w, mv.w);
    }

    // combine (verbatim math)
    float4 hv = ((const float4*)(h + (size_t)warp * HD))[lane];
    float m0 = __shfl_sync(0xffffffffu, mv.x, 0);
    float pm = warp_sum(((lane == 0) ? 0.f : mv.x * mv.x) + mv.y * mv.y + mv.z * mv.z + mv.w * mv.w);
    float denom = sqrtf(fmaxf(m0 * m0 - pm, 1e-9f));
    float r = sc / denom;
    float axx = r * mv.x, ay = r * mv.y, az = r * mv.z, aw = r * mv.w;
    float ssum = warp_sum(((lane == 0) ? 0.f : axx * axx) + ay * ay + az * az + aw * aw);
    float t = sqrtf(c + ssum);
    float yn_a = fmaxf(sqrtf(ssum), 1e-9f);
    float d1 = sc * acoshf(fmaxf(t / sc, 1.f + EPSF));
    float cA = d1 / yn_a;
    float ph = warp_sum(((lane == 0) ? 0.f : hv.x * hv.x) + hv.y * hv.y + hv.z * hv.z + hv.w * hv.w);
    float hp0 = sqrtf(c + ph);
    float yn_h = fmaxf(sqrtf(ph), 1e-9f);
    float d2 = sc * acoshf(fmaxf(hp0 / sc, 1.f + EPSF));
    float cH = (1.f + ep) * d2 / yn_h;
    float4 vv;
    vv.x = (lane == 0) ? 0.f : cA * axx + cH * hv.x;
    vv.y = cA * ay + cH * hv.y;
    vv.z = cA * az + cH * hv.z;
    vv.w = cA * aw + cH * hv.w;
    float pv = warp_sum(vv.x * vv.x + vv.y * vv.y + vv.z * vv.z + vv.w * vv.w);
    float n = fmaxf(sqrtf(pv), 1e-9f);
    float sh = sc * sinhf(n / sc) / n;
    float4 o;
    o.x = (lane == 0) ? 0.f : sh * vv.x;
    o.y = sh * vv.y; o.z = sh * vv.z; o.w = sh * vv.w;
    float so = warp_sum(((lane == 0) ? 0.f : o.x * o.x) + o.y * o.y + o.z * o.z + o.w * o.w);
    float x0 = sqrtf(c + so);
    if (lane == 0) o.x = x0;
    ((float4*)(U + (size_t)warp * HD))[lane] = logmap_quad(o, so, x0, c, sc, lane);
}

template <bool WRITE_H, bool POOL>
__global__ void mlp_epi_kernel(const float* __restrict__ P, float* __restrict__ H,
                               float* __restrict__ U, const float* __restrict__ cptr,
                               const int* __restrict__ batch, float* __restrict__ out,
                               int loff) {
    int warp = (blockIdx.x * blockDim.x + threadIdx.x) >> 5;
    int lane = threadIdx.x & 31;
    if (warp >= NN) return;
    float c = cptr[0], sc = sqrtf(c);
    float4 v = ((const float4*)(P + (size_t)warp * HD))[lane];
    float s = warp_sum(v.x * v.x + v.y * v.y + v.z * v.z + v.w * v.w);
    float n1 = fmaxf(sqrtf(s), 1e-9f);
    float sh1 = sc * sinhf(n1 / sc) / n1;
    float sx = sh1 * v.x, sy = sh1 * v.y, sz = sh1 * v.z, sw = sh1 * v.w;
    float ssum = warp_sum(sx * sx + sy * sy + sz * sz + sw * sw);
    float x0p = sqrtf(c + ssum);
    float ynp = fmaxf(sqrtf(ssum), 1e-9f);
    float dp = sc * acoshf(fmaxf(x0p / sc, 1.f + EPSF));
    float cf = dp / ynp;
    float tx = tanhf(cf * sx), ty = tanhf(cf * sy), tz = tanhf(cf * sz), tw = tanhf(cf * sw);
    float s2 = warp_sum(tx * tx + ty * ty + tz * tz + tw * tw);
    float n2 = fmaxf(sqrtf(s2), 1e-9f);
    float sh2 = sc * sinhf(n2 / sc) / n2;
    float wprev = __shfl_up_sync(0xffffffffu, tw, 1);
    float x0 = sc * coshf(n2 / sc);
    float4 o;
    o.x = (lane == 0) ? x0 : sh2 * wprev;
    o.y = sh2 * tx; o.z = sh2 * ty; o.w = sh2 * tz;
    if (WRITE_H) ((float4*)(H + (size_t)warp * HD))[lane] = o;
    float sl = warp_sum(((lane == 0) ? 0.f : o.x * o.x) + o.y * o.y + o.z * o.z + o.w * o.w);
    float yn = fmaxf(sqrtf(sl), 1e-9f);
    float d = sc * acoshf(fmaxf(x0 / sc, 1.f + EPSF));
    float a = d / yn;
    float nx = __shfl_down_sync(0xffffffffu, o.x, 1);
    float4 u;
    u.x = a * o.y; u.y = a * o.z; u.z = a * o.w;
    u.w = (lane == 31) ? 0.f : a * nx;
    ((float4*)(U + (size_t)warp * HD))[lane] = u;
    if (POOL) {
        int g = batch[warp];
        red_v4(out + (size_t)g * (2 * HD) + loff + lane * 4,
               (lane == 0) ? 0.f : a * o.x, a * o.y, a * o.z, a * o.w);
    }
}

// ---------------- host launcher ----------------
extern "C" void kernel_launch(void* const* d_in, const int* in_sizes, int n_in,
                              void* d_out, int out_size) {
    (void)in_sizes; (void)n_in; (void)out_size;
    const float* x     = (const float*)d_in[0];
    const float* c     = (const float*)d_in[1];
    const float* w_in  = (const float*)d_in[2];
    const float* att_w = (const float*)d_in[3];
    const float* att_b = (const float*)d_in[4];
    const float* eps   = (const float*)d_in[5];
    const float* mlp_w = (const float*)d_in[6];
    const float* mlp_b = (const float*)d_in[7];
    const int*   ei    = (const int*)d_in[8];
    const int*   batch = (const int*)d_in[9];
    float* out = (float*)d_out;

    float *ph, *pu, *pp, *phl, *pwf, *pwfin;
    int* pcnt;
    cudaGetSymbolAddress((void**)&ph, g_h);
    cudaGetSymbolAddress((void**)&pu, g_u);
    cudaGetSymbolAddress((void**)&pp, g_p);
    cudaGetSymbolAddress((void**)&phl, g_hl);
    cudaGetSymbolAddress((void**)&pwf, g_wf);
    cudaGetSymbolAddress((void**)&pwfin, g_wfin);
    cudaGetSymbolAddress((void**)&pcnt, g_cnt);

    const int NB = (NN + 7) / 8;         // warp-per-node blocks
    const int TB64 = (NN + 63) / 64;     // input GEMM blocks (64 rows)
    const int TB128 = (NN + 127) / 128;  // m32 GEMM blocks (128 rows)
    const int SCB = (NN + 255) / 256;    // scan blocks

    zero4_kernel<<<(GG * 2 * HD / 4 + 255) / 256, 256>>>((float4*)out, GG * 2 * HD / 4);
    prep_weights<<<(6 * HD * HD + 255) / 256, 256>>>(att_w, mlp_w);
    prep_win<<<(IN_DIM * HD + 255) / 256, 256>>>(w_in);
    prep_wf<<<(6 * 8 * 16 * 32 + 255) / 256, 256>>>();
    prep_wfin<<<(13 * 16 * 32 + 255) / 256, 256>>>();

    // CSR build (once; reused by both layers)
    zeroi_kernel<<<SCB, 256>>>(pcnt, NN);
    hist_kernel<<<(EE + 255) / 256, 256>>>(ei);
    scan1_kernel<<<SCB, 256>>>();
    scan2_kernel<<<1, 256>>>(SCB);
    scan3_kernel<<<SCB, 256>>>();
    scatter_kernel<<<(EE + 255) / 256, 256>>>(ei);

    // input: h0 = proj(expmap0([0, x @ w_in])), u0 = logmap0(h0)
    gemm_tc_in<<<TB64, 256>>>(x, (const uint4*)pwfin, pp);
    expmap_u_kernel<<<NB, 256>>>(pp, ph, pu, c);

    for (int l = 0; l < 2; l++) {
        // attention linear: hl = proj(expmap0(u @ W + b))
        gemm_tc128<true><<<TB128, 256>>>(pu, (const uint4*)(pwf + (size_t)l * 8 * 16 * 32 * 4),
                                         att_b + l * DD, pp);
        expmap_kernel<<<NB, 256>>>(pp, phl, c);
        // centroid + GIN combine -> u
        agg_combine_kernel<<<NB, 256>>>(phl, ph, pu, c, eps, l);
        // MLP 0
        gemm_tc128<true><<<TB128, 256>>>(pu, (const uint4*)(pwf + (size_t)(2 + l * 2 + 0) * 8 * 16 * 32 * 4),
                                         mlp_b + (l * 2 + 0) * DD, pp);
        mlp_epi_kernel<false, false><<<NB, 256>>>(pp, nullptr, pu, c, nullptr, nullptr, 0);
        // MLP 1 (+ layer output + pooled readout)
        gemm_tc128<true><<<TB128, 256>>>(pu, (const uint4*)(pwf + (size_t)(2 + l * 2 + 1) * 8 * 16 * 32 * 4),
                                         mlp_b + (l * 2 + 1) * DD, pp);
        mlp_epi_kernel<true, true><<<NB, 256>>>(pp, ph, pu, c, batch, out, l * HD);
    }
}

// round 15
// speedup vs baseline: 1.1094x; 1.0200x over previous
#include <cuda_runtime.h>
#include <math.h>
#include <stdint.h>

#define NN 50000
#define EE 800000
#define IN_DIM 200
#define HD 128
#define DD 127
#define GG 512
#define EPSF 1e-5f

// ---------------- scratch (device globals; no allocation allowed) ----------------
__device__ float g_h[NN * HD];      // hyperboloid node features
__device__ float g_u[NN * HD];      // logmap0 spatial (slots 0..126, slot127 = 0)
__device__ float g_p[NN * HD];      // GEMM output
__device__ float g_hl[NN * HD];     // attention-linear hyperboloid points
__device__ float g_wt[6 * HD * HD];   // transposed+padded weights (k-major)
__device__ float g_wtin[IN_DIM * HD];
__device__ float g_wf[6 * 8 * 16 * 32 * 4];     // bf16-split fragment weights (K=128 mats)
__device__ float g_wfin[13 * 16 * 32 * 4];      // bf16-split fragment input weights (K=200->208)
__device__ int   g_cnt[NN];
__device__ int   g_rowptr[NN + 1];
__device__ int   g_cur[NN];
__device__ int   g_dstidx[EE];
__device__ int   g_blksum[256];
__device__ int   g_blkoff[256];

__device__ __forceinline__ float warp_sum(float v) {
#pragma unroll
    for (int o = 16; o; o >>= 1) v += __shfl_xor_sync(0xffffffffu, v, o);
    return v;
}

__device__ __forceinline__ void red_v4(float* p, float a, float b, float c, float d) {
    asm volatile("red.global.add.v4.f32 [%0], {%1,%2,%3,%4};"
                 :: "l"(p), "f"(a), "f"(b), "f"(c), "f"(d) : "memory");
}

// m16n8k16 bf16 MMA, fp32 accumulate (A row-major frag, B col-major frag)
__device__ __forceinline__ void mma_bf16(float* d, uint32_t a0, uint32_t a1,
                                         uint32_t a2, uint32_t a3,
                                         uint32_t b0, uint32_t b1) {
    asm("mma.sync.aligned.m16n8k16.row.col.f32.bf16.bf16.f32 "
        "{%0,%1,%2,%3}, {%4,%5,%6,%7}, {%8,%9}, {%0,%1,%2,%3};"
        : "+f"(d[0]), "+f"(d[1]), "+f"(d[2]), "+f"(d[3])
        : "r"(a0), "r"(a1), "r"(a2), "r"(a3), "r"(b0), "r"(b1));
}

__device__ __forceinline__ uint32_t bf16x2_hi(float x, float y) {
    uint32_t r;
    asm("cvt.rn.bf16x2.f32 %0, %1, %2;" : "=r"(r) : "f"(y), "f"(x));
    return r;
}
__device__ __forceinline__ uint32_t bf16x2_lo(float x, float y, uint32_t h) {
    float h0 = __uint_as_float(h << 16);
    float h1 = __uint_as_float(h & 0xFFFF0000u);
    return bf16x2_hi(x - h0, y - h1);
}

// ---------------- utility kernels ----------------
__global__ void zero4_kernel(float4* __restrict__ p, int n4) {
    int i = blockIdx.x * blockDim.x + threadIdx.x;
    if (i < n4) p[i] = make_float4(0.f, 0.f, 0.f, 0.f);
}

__global__ void zeroi_kernel(int* __restrict__ p, int n) {
    int i = blockIdx.x * blockDim.x + threadIdx.x;
    if (i < n) p[i] = 0;
}

__global__ void prep_weights(const float* __restrict__ att_w, const float* __restrict__ mlp_w) {
    int idx = blockIdx.x * blockDim.x + threadIdx.x;
    if (idx >= 6 * HD * HD) return;
    int w = idx >> 14;
    int k = (idx >> 7) & 127;
    int j = idx & 127;
    float val = 0.f;
    if (k < DD && j < DD) {
        const float* src = (w < 2) ? (att_w + w * DD * DD) : (mlp_w + (w - 2) * DD * DD);
        val = src[j * DD + k];
    }
    g_wt[idx] = val;
}

__global__ void prep_win(const float* __restrict__ w_in) {
    int idx = blockIdx.x * blockDim.x + threadIdx.x;
    if (idx >= IN_DIM * HD) return;
    int k = idx >> 7;
    int j = idx & 127;
    g_wtin[idx] = (j < DD) ? w_in[k * DD + j] : 0.f;
}

// bf16-split fragment weights: uint4 (b0h, b1h, b0l, b1l) per (mat, k16, tile, lane)
__global__ void prep_wf() {
    int idx = blockIdx.x * blockDim.x + threadIdx.x;
    if (idx >= 6 * 8 * 16 * 32) return;
    int lane = idx & 31;
    int tile = (idx >> 5) & 15;
    int k16 = (idx >> 9) & 7;
    int mat = idx >> 12;
    int gg = lane >> 2, t4 = lane & 3;
    int k0 = k16 * 16 + 2 * t4;
    int n = tile * 8 + gg;
    const float* W = g_wt + mat * HD * HD;
    float w00 = W[k0 * HD + n],       w01 = W[(k0 + 1) * HD + n];
    float w10 = W[(k0 + 8) * HD + n], w11 = W[(k0 + 9) * HD + n];
    uint4 o;
    o.x = bf16x2_hi(w00, w01);
    o.y = bf16x2_hi(w10, w11);
    o.z = bf16x2_lo(w00, w01, o.x);
    o.w = bf16x2_lo(w10, w11, o.y);
    ((uint4*)g_wf)[idx] = o;
}

__global__ void prep_wfin() {
    int idx = blockIdx.x * blockDim.x + threadIdx.x;
    if (idx >= 13 * 16 * 32) return;
    int lane = idx & 31;
    int tile = (idx >> 5) & 15;
    int k16 = idx >> 9;                 // 0..12
    int gg = lane >> 2, t4 = lane & 3;
    int k0 = k16 * 16 + 2 * t4;
    int n = tile * 8 + gg;
    float w00 = (k0 < IN_DIM)     ? g_wtin[k0 * HD + n] : 0.f;
    float w01 = (k0 + 1 < IN_DIM) ? g_wtin[(k0 + 1) * HD + n] : 0.f;
    float w10 = (k0 + 8 < IN_DIM) ? g_wtin[(k0 + 8) * HD + n] : 0.f;
    float w11 = (k0 + 9 < IN_DIM) ? g_wtin[(k0 + 9) * HD + n] : 0.f;
    uint4 o;
    o.x = bf16x2_hi(w00, w01);
    o.y = bf16x2_hi(w10, w11);
    o.z = bf16x2_lo(w00, w01, o.x);
    o.w = bf16x2_lo(w10, w11, o.y);
    ((uint4*)g_wfin)[idx] = o;
}

// ---------------- CSR build ----------------
__global__ void hist_kernel(const int* __restrict__ ei) {
    int e = blockIdx.x * blockDim.x + threadIdx.x;
    if (e < EE) atomicAdd(&g_cnt[ei[e]], 1);
}

__global__ void scan1_kernel() {
    __shared__ int sh[256];
    int t = threadIdx.x;
    int idx = blockIdx.x * 256 + t;
    int v = (idx < NN) ? g_cnt[idx] : 0;
    sh[t] = v;
    __syncthreads();
#pragma unroll
    for (int d = 1; d < 256; d <<= 1) {
        int o = (t >= d) ? sh[t - d] : 0;
        __syncthreads();
        sh[t] += o;
        __syncthreads();
    }
    if (idx < NN) g_rowptr[idx] = sh[t] - v;
    if (t == 255) g_blksum[blockIdx.x] = sh[255];
}

__global__ void scan2_kernel(int nblk) {
    __shared__ int sh[256];
    int t = threadIdx.x;
    int v = (t < nblk) ? g_blksum[t] : 0;
    sh[t] = v;
    __syncthreads();
#pragma unroll
    for (int d = 1; d < 256; d <<= 1) {
        int o = (t >= d) ? sh[t - d] : 0;
        __syncthreads();
        sh[t] += o;
        __syncthreads();
    }
    if (t < nblk) g_blkoff[t] = sh[t] - v;
    if (t == 255) g_rowptr[NN] = sh[255];
}

__global__ void scan3_kernel() {
    int idx = blockIdx.x * 256 + threadIdx.x;
    if (idx >= NN) return;
    int r = g_rowptr[idx] + g_blkoff[blockIdx.x];
    g_rowptr[idx] = r;
    g_cur[idx] = r;
}

__global__ void scatter_kernel(const int* __restrict__ ei) {
    int e = blockIdx.x * blockDim.x + threadIdx.x;
    if (e >= EE) return;
    int s = ei[e];
    int pos = atomicAdd(&g_cur[s], 1);
    g_dstidx[pos] = ei[EE + e];
}

// ---------------- split-bf16 TC GEMM, K=128, m32-per-warp (R11/R12 winner) ----------------
template <bool HASBIAS>
__global__ void __launch_bounds__(256) gemm_tc128(const float* __restrict__ U,
                                                  const uint4* __restrict__ WF,
                                                  const float* __restrict__ bias,
                                                  float* __restrict__ P) {
    int tid = threadIdx.x;
    int lane = tid & 31;
    int w = tid >> 5;
    int wm = w & 3;
    int wn = w >> 2;
    int row0 = blockIdx.x * 128;
    int gg = lane >> 2, t4 = lane & 3;
    int ra = row0 + 32 * wm + gg;   // 4 fragment rows: ra, ra+8, ra+16, ra+24
    const float* A0 = U + (size_t)min(ra,      NN - 1) * HD;
    const float* A1 = U + (size_t)min(ra + 8,  NN - 1) * HD;
    const float* A2 = U + (size_t)min(ra + 16, NN - 1) * HD;
    const float* A3 = U + (size_t)min(ra + 24, NN - 1) * HD;

    float acc[8][2][4];   // [n8-tile][m16-half][4]
#pragma unroll
    for (int t = 0; t < 8; t++)
#pragma unroll
        for (int m = 0; m < 2; m++) {
            acc[t][m][0] = 0.f; acc[t][m][1] = 0.f;
            acc[t][m][2] = 0.f; acc[t][m][3] = 0.f;
        }

    for (int k16 = 0; k16 < 8; k16++) {
        int c0 = k16 * 16 + 2 * t4;
        int c1 = c0 + 8;
        float2 f00 = *(const float2*)&A0[c0], f01 = *(const float2*)&A0[c1];
        float2 f10 = *(const float2*)&A1[c0], f11 = *(const float2*)&A1[c1];
        float2 f20 = *(const float2*)&A2[c0], f21 = *(const float2*)&A2[c1];
        float2 f30 = *(const float2*)&A3[c0], f31 = *(const float2*)&A3[c1];
        uint32_t h0 = bf16x2_hi(f00.x, f00.y), h1 = bf16x2_hi(f10.x, f10.y);
        uint32_t h2 = bf16x2_hi(f01.x, f01.y), h3 = bf16x2_hi(f11.x, f11.y);
        uint32_t l0 = bf16x2_lo(f00.x, f00.y, h0), l1 = bf16x2_lo(f10.x, f10.y, h1);
        uint32_t l2 = bf16x2_lo(f01.x, f01.y, h2), l3 = bf16x2_lo(f11.x, f11.y, h3);
        uint32_t h4 = bf16x2_hi(f20.x, f20.y), h5 = bf16x2_hi(f30.x, f30.y);
        uint32_t h6 = bf16x2_hi(f21.x, f21.y), h7 = bf16x2_hi(f31.x, f31.y);
        uint32_t l4 = bf16x2_lo(f20.x, f20.y, h4), l5 = bf16x2_lo(f30.x, f30.y, h5);
        uint32_t l6 = bf16x2_lo(f21.x, f21.y, h6), l7 = bf16x2_lo(f31.x, f31.y, h7);
        const uint4* wf = WF + ((size_t)k16 * 16 + wn * 8) * 32 + lane;
#pragma unroll
        for (int t = 0; t < 8; t++) {
            uint4 bv = wf[t * 32];   // (b0h, b1h, b0l, b1l) — reused for both m-halves
            mma_bf16(acc[t][0], h0, h1, h2, h3, bv.x, bv.y);
            mma_bf16(acc[t][0], h0, h1, h2, h3, bv.z, bv.w);
            mma_bf16(acc[t][0], l0, l1, l2, l3, bv.x, bv.y);
            mma_bf16(acc[t][1], h4, h5, h6, h7, bv.x, bv.y);
            mma_bf16(acc[t][1], h4, h5, h6, h7, bv.z, bv.w);
            mma_bf16(acc[t][1], l4, l5, l6, l7, bv.x, bv.y);
        }
    }

#pragma unroll
    for (int t = 0; t < 8; t++) {
        int j0 = 64 * wn + 8 * t + 2 * t4;   // even, 0..126
        float b0 = 0.f, b1 = 0.f;
        if (HASBIAS) {
            b0 = bias[j0];
            b1 = (j0 + 1 < DD) ? bias[j0 + 1] : 0.f;
        }
#pragma unroll
        for (int m = 0; m < 2; m++) {
            float d0 = acc[t][m][0] + b0, d1 = acc[t][m][1] + b1;
            float d2 = acc[t][m][2] + b0, d3 = acc[t][m][3] + b1;
            if (j0 + 1 == 127) { d1 = 0.f; d3 = 0.f; }  // padding col
            int r0 = ra + 16 * m;
            int r1 = r0 + 8;
            if (r0 < NN) *(float2*)&P[(size_t)r0 * HD + j0] = make_float2(d0, d1);
            if (r1 < NN) *(float2*)&P[(size_t)r1 * HD + j0] = make_float2(d2, d3);
        }
    }
}

// ---------------- input GEMM K=200 (direct path, runs once; unchanged) ----------------
__global__ void __launch_bounds__(256) gemm_tc_in(const float* __restrict__ U,
                                                  const uint4* __restrict__ WF,
                                                  float* __restrict__ P) {
    constexpr int K = IN_DIM;
    constexpr int K16 = (K + 15) / 16;   // 13
    int tid = threadIdx.x;
    int lane = tid & 31;
    int w = tid >> 5;
    int wm = w & 3;
    int wn = w >> 2;
    int row0 = blockIdx.x * 64;
    int gg = lane >> 2, t4 = lane & 3;
    int ra = row0 + 16 * wm + gg;
    int rb = ra + 8;
    const float* A0 = U + (size_t)min(ra, NN - 1) * K;
    const float* A1 = U + (size_t)min(rb, NN - 1) * K;

    float acc[8][4];
#pragma unroll
    for (int t = 0; t < 8; t++) {
        acc[t][0] = 0.f; acc[t][1] = 0.f; acc[t][2] = 0.f; acc[t][3] = 0.f;
    }

    for (int k16 = 0; k16 < K16; k16++) {
        int kc = k16 * 16;
        int c0 = kc + 2 * t4;
        int c1 = kc + 8 + 2 * t4;
        float2 fa0, fa1, fa2, fa3;
        if (k16 == K16 - 1) {
            fa0.x = (c0 < K) ? A0[c0] : 0.f;     fa0.y = (c0 + 1 < K) ? A0[c0 + 1] : 0.f;
            fa1.x = (c0 < K) ? A1[c0] : 0.f;     fa1.y = (c0 + 1 < K) ? A1[c0 + 1] : 0.f;
            fa2.x = (c1 < K) ? A0[c1] : 0.f;     fa2.y = (c1 + 1 < K) ? A0[c1 + 1] : 0.f;
            fa3.x = (c1 < K) ? A1[c1] : 0.f;     fa3.y = (c1 + 1 < K) ? A1[c1 + 1] : 0.f;
        } else {
            fa0 = *(const float2*)&A0[c0];
            fa1 = *(const float2*)&A1[c0];
            fa2 = *(const float2*)&A0[c1];
            fa3 = *(const float2*)&A1[c1];
        }
        uint32_t h0 = bf16x2_hi(fa0.x, fa0.y), h1 = bf16x2_hi(fa1.x, fa1.y);
        uint32_t h2 = bf16x2_hi(fa2.x, fa2.y), h3 = bf16x2_hi(fa3.x, fa3.y);
        uint32_t l0 = bf16x2_lo(fa0.x, fa0.y, h0), l1 = bf16x2_lo(fa1.x, fa1.y, h1);
        uint32_t l2 = bf16x2_lo(fa2.x, fa2.y, h2), l3 = bf16x2_lo(fa3.x, fa3.y, h3);
        const uint4* wf = WF + ((size_t)k16 * 16 + wn * 8) * 32 + lane;
#pragma unroll
        for (int t = 0; t < 8; t++) {
            uint4 bv = wf[t * 32];
            mma_bf16(acc[t], h0, h1, h2, h3, bv.x, bv.y);
            mma_bf16(acc[t], h0, h1, h2, h3, bv.z, bv.w);
            mma_bf16(acc[t], l0, l1, l2, l3, bv.x, bv.y);
        }
    }

#pragma unroll
    for (int t = 0; t < 8; t++) {
        int j0 = 64 * wn + 8 * t + 2 * t4;
        float d0 = acc[t][0], d1 = acc[t][1];
        float d2 = acc[t][2], d3 = acc[t][3];
        if (j0 + 1 == 127) { d1 = 0.f; d3 = 0.f; }
        if (ra < NN) *(float2*)&P[(size_t)ra * HD + j0] = make_float2(d0, d1);
        if (rb < NN) *(float2*)&P[(size_t)rb * HD + j0] = make_float2(d2, d3);
    }
}

// ---------------- warp-per-node elementwise kernels (unchanged) ----------------

__device__ __forceinline__ float4 logmap_quad(float4 o, float ss, float x0,
                                              float c, float sc, int lane) {
    float yn = fmaxf(sqrtf(ss), 1e-9f);
    float d = sc * acoshf(fmaxf(x0 / sc, 1.f + EPSF));
    float a = d / yn;
    float nx = __shfl_down_sync(0xffffffffu, o.x, 1);
    float4 u;
    u.x = a * o.y; u.y = a * o.z; u.z = a * o.w;
    u.w = (lane == 31) ? 0.f : a * nx;
    return u;
}

__global__ void expmap_kernel(const float* __restrict__ P, float* __restrict__ out,
                              const float* __restrict__ cptr) {
    int warp = (blockIdx.x * blockDim.x + threadIdx.x) >> 5;
    int lane = threadIdx.x & 31;
    if (warp >= NN) return;
    float c = cptr[0], sc = sqrtf(c);
    float4 v = ((const float4*)(P + (size_t)warp * HD))[lane];
    float s = warp_sum(v.x * v.x + v.y * v.y + v.z * v.z + v.w * v.w);
    float n = fmaxf(sqrtf(s), 1e-9f);
    float sh = sc * sinhf(n / sc) / n;
    float wprev = __shfl_up_sync(0xffffffffu, v.w, 1);
    float4 o;
    o.x = (lane == 0) ? 0.f : sh * wprev;
    o.y = sh * v.x; o.z = sh * v.y; o.w = sh * v.z;
    float ss = warp_sum(((lane == 0) ? 0.f : o.x * o.x) + o.y * o.y + o.z * o.z + o.w * o.w);
    if (lane == 0) o.x = sqrtf(c + ss);
    ((float4*)(out + (size_t)warp * HD))[lane] = o;
}

__global__ void expmap_u_kernel(const float* __restrict__ P, float* __restrict__ H,
                                float* __restrict__ U, const float* __restrict__ cptr) {
    int warp = (blockIdx.x * blockDim.x + threadIdx.x) >> 5;
    int lane = threadIdx.x & 31;
    if (warp >= NN) return;
    float c = cptr[0], sc = sqrtf(c);
    float4 v = ((const float4*)(P + (size_t)warp * HD))[lane];
    float s = warp_sum(v.x * v.x + v.y * v.y + v.z * v.z + v.w * v.w);
    float n = fmaxf(sqrtf(s), 1e-9f);
    float sh = sc * sinhf(n / sc) / n;
    float wprev = __shfl_up_sync(0xffffffffu, v.w, 1);
    float4 o;
    o.x = (lane == 0) ? 0.f : sh * wprev;
    o.y = sh * v.x; o.z = sh * v.y; o.w = sh * v.z;
    float ss = warp_sum(((lane == 0) ? 0.f : o.x * o.x) + o.y * o.y + o.z * o.z + o.w * o.w);
    float x0 = sqrtf(c + ss);
    if (lane == 0) o.x = x0;
    ((float4*)(H + (size_t)warp * HD))[lane] = o;
    ((float4*)(U + (size_t)warp * HD))[lane] = logmap_quad(o, ss, x0, c, sc, lane);
}

// warp per node: CSR centroid (2-edge ILP) + GIN combine; emits u = logmap0(result).
__global__ void agg_combine_kernel(const float* __restrict__ hl, const float* __restrict__ h,
                                   float* __restrict__ U, const float* __restrict__ cptr,
                                   const float* __restrict__ epsp, int l) {
    int warp = (blockIdx.x * blockDim.x + threadIdx.x) >> 5;
    int lane = threadIdx.x & 31;
    if (warp >= NN) return;
    float c = cptr[0], sc = sqrtf(c), ep = epsp[l];
    bool c1 = (sc == 1.f);
    int beg = g_rowptr[warp], end = g_rowptr[warp + 1];
    float4 a = ((const float4*)(hl + (size_t)warp * HD))[lane];
    float ax0 = (lane == 0) ? -a.x : a.x;
    float4 mv = make_float4(0.f, 0.f, 0.f, 0.f);

    int e = beg;
    for (; e + 1 < end; e += 2) {
        int d0i = g_dstidx[e];
        int d1i = g_dstidx[e + 1];
        float4 b0 = ((const float4*)(hl + (size_t)d0i * HD))[lane];
        float4 b1 = ((const float4*)(hl + (size_t)d1i * HD))[lane];
        float4 hv0 = ((const float4*)(h + (size_t)d0i * HD))[lane];
        float4 hv1 = ((const float4*)(h + (size_t)d1i * HD))[lane];
        float p0 = ax0 * b0.x + a.y * b0.y + a.z * b0.z + a.w * b0.w;
        float p1 = ax0 * b1.x + a.y * b1.y + a.z * b1.z + a.w * b1.w;
#pragma unroll
        for (int o = 16; o; o >>= 1) {
            p0 += __shfl_xor_sync(0xffffffffu, p0, o);
            p1 += __shfl_xor_sync(0xffffffffu, p1, o);
        }
        float val0 = fmaxf(-p0 / c, 1.f + EPSF);
        float val1 = fmaxf(-p1 / c, 1.f + EPSF);
        float att0 = c1 ? (1.f / (val0 + sqrtf(val0 * val0 - 1.f)))
                        : expf(-sc * acoshf(val0));
        float att1 = c1 ? (1.f / (val1 + sqrtf(val1 * val1 - 1.f)))
                        : expf(-sc * acoshf(val1));
        mv.x = fmaf(att0, hv0.x, mv.x);
        mv.y = fmaf(att0, hv0.y, mv.y);
        mv.z = fmaf(att0, hv0.z, mv.z);
        mv.w = fmaf(att0, hv0.w, mv.w);
        mv.x = fmaf(att1, hv1.x, mv.x);
        mv.y = fmaf(att1, hv1.y, mv.y);
        mv.z = fmaf(att1, hv1.z, mv.z);
        mv.w = fmaf(att1, hv1.w, mv.w);
    }
    if (e < end) {
        int di = g_dstidx[e];
        float4 b = ((const float4*)(hl + (size_t)di * HD))[lane];
        float4 hv = ((const float4*)(h + (size_t)di * HD))[lane];
        float p = ax0 * b.x + a.y * b.y + a.z * b.z + a.w * b.w;
        p = warp_sum(p);
        float val = fmaxf(-p / c, 1.f + EPSF);
        float att = c1 ? (1.f / (val + sqrtf(val * val - 1.f)))
                       : expf(-sc * acoshf(val));
        mv.x = fmaf(att, hv.x, mv.x);
        mv.y = fmaf(att, hv.y, mv.y);
        mv.z = fmaf(att, hv.z, mv.z);
        mv.w = fmaf(att, hv.w, mv.w);
    }

    float4 hv = ((const float4*)(h + (size_t)warp * HD))[lane];
    float m0 = __shfl_sync(0xffffffffu, mv.x, 0);
    float pm = warp_sum(((lane == 0) ? 0.f : mv.x * mv.x) + mv.y * mv.y + mv.z * mv.z + mv.w * mv.w);
    float denom = sqrtf(fmaxf(m0 * m0 - pm, 1e-9f));
    float r = sc / denom;
    float axx = r * mv.x, ay = r * mv.y, az = r * mv.z, aw = r * mv.w;
    float ssum = warp_sum(((lane == 0) ? 0.f : axx * axx) + ay * ay + az * az + aw * aw);
    float t = sqrtf(c + ssum);
    float yn_a = fmaxf(sqrtf(ssum), 1e-9f);
    float d1 = sc * acoshf(fmaxf(t / sc, 1.f + EPSF));
    float cA = d1 / yn_a;
    float ph = warp_sum(((lane == 0) ? 0.f : hv.x * hv.x) + hv.y * hv.y + hv.z * hv.z + hv.w * hv.w);
    float hp0 = sqrtf(c + ph);
    float yn_h = fmaxf(sqrtf(ph), 1e-9f);
    float d2 = sc * acoshf(fmaxf(hp0 / sc, 1.f + EPSF));
    float cH = (1.f + ep) * d2 / yn_h;
    float4 vv;
    vv.x = (lane == 0) ? 0.f : cA * axx + cH * hv.x;
    vv.y = cA * ay + cH * hv.y;
    vv.z = cA * az + cH * hv.z;
    vv.w = cA * aw + cH * hv.w;
    float pv = warp_sum(vv.x * vv.x + vv.y * vv.y + vv.z * vv.z + vv.w * vv.w);
    float n = fmaxf(sqrtf(pv), 1e-9f);
    float sh = sc * sinhf(n / sc) / n;
    float4 o;
    o.x = (lane == 0) ? 0.f : sh * vv.x;
    o.y = sh * vv.y; o.z = sh * vv.z; o.w = sh * vv.w;
    float so = warp_sum(((lane == 0) ? 0.f : o.x * o.x) + o.y * o.y + o.z * o.z + o.w * o.w);
    float x0 = sqrtf(c + so);
    if (lane == 0) o.x = x0;
    ((float4*)(U + (size_t)warp * HD))[lane] = logmap_quad(o, so, x0, c, sc, lane);
}

template <bool WRITE_H, bool POOL>
__global__ void mlp_epi_kernel(const float* __restrict__ P, float* __restrict__ H,
                               float* __restrict__ U, const float* __restrict__ cptr,
                               const int* __restrict__ batch, float* __restrict__ out,
                               int loff) {
    int warp = (blockIdx.x * blockDim.x + threadIdx.x) >> 5;
    int lane = threadIdx.x & 31;
    if (warp >= NN) return;
    float c = cptr[0], sc = sqrtf(c);
    float4 v = ((const float4*)(P + (size_t)warp * HD))[lane];
    float s = warp_sum(v.x * v.x + v.y * v.y + v.z * v.z + v.w * v.w);
    float n1 = fmaxf(sqrtf(s), 1e-9f);
    float sh1 = sc * sinhf(n1 / sc) / n1;
    float sx = sh1 * v.x, sy = sh1 * v.y, sz = sh1 * v.z, sw = sh1 * v.w;
    float ssum = warp_sum(sx * sx + sy * sy + sz * sz + sw * sw);
    float x0p = sqrtf(c + ssum);
    float ynp = fmaxf(sqrtf(ssum), 1e-9f);
    float dp = sc * acoshf(fmaxf(x0p / sc, 1.f + EPSF));
    float cf = dp / ynp;
    float tx = tanhf(cf * sx), ty = tanhf(cf * sy), tz = tanhf(cf * sz), tw = tanhf(cf * sw);
    float s2 = warp_sum(tx * tx + ty * ty + tz * tz + tw * tw);
    float n2 = fmaxf(sqrtf(s2), 1e-9f);
    float sh2 = sc * sinhf(n2 / sc) / n2;
    float wprev = __shfl_up_sync(0xffffffffu, tw, 1);
    float x0 = sc * coshf(n2 / sc);
    float4 o;
    o.x = (lane == 0) ? x0 : sh2 * wprev;
    o.y = sh2 * tx; o.z = sh2 * ty; o.w = sh2 * tz;
    if (WRITE_H) ((float4*)(H + (size_t)warp * HD))[lane] = o;
    float sl = warp_sum(((lane == 0) ? 0.f : o.x * o.x) + o.y * o.y + o.z * o.z + o.w * o.w);
    float yn = fmaxf(sqrtf(sl), 1e-9f);
    float d = sc * acoshf(fmaxf(x0 / sc, 1.f + EPSF));
    float a = d / yn;
    float nx = __shfl_down_sync(0xffffffffu, o.x, 1);
    float4 u;
    u.x = a * o.y; u.y = a * o.z; u.z = a * o.w;
    u.w = (lane == 31) ? 0.f : a * nx;
    ((float4*)(U + (size_t)warp * HD))[lane] = u;
    if (POOL) {
        int g = batch[warp];
        red_v4(out + (size_t)g * (2 * HD) + loff + lane * 4,
               (lane == 0) ? 0.f : a * o.x, a * o.y, a * o.z, a * o.w);
    }
}

// ---------------- host launcher ----------------
extern "C" void kernel_launch(void* const* d_in, const int* in_sizes, int n_in,
                              void* d_out, int out_size) {
    (void)in_sizes; (void)n_in; (void)out_size;
    const float* x     = (const float*)d_in[0];
    const float* c     = (const float*)d_in[1];
    const float* w_in  = (const float*)d_in[2];
    const float* att_w = (const float*)d_in[3];
    const float* att_b = (const float*)d_in[4];
    const float* eps   = (const float*)d_in[5];
    const float* mlp_w = (const float*)d_in[6];
    const float* mlp_b = (const float*)d_in[7];
    const int*   ei    = (const int*)d_in[8];
    const int*   batch = (const int*)d_in[9];
    float* out = (float*)d_out;

    float *ph, *pu, *pp, *phl, *pwf, *pwfin;
    int* pcnt;
    cudaGetSymbolAddress((void**)&ph, g_h);
    cudaGetSymbolAddress((void**)&pu, g_u);
    cudaGetSymbolAddress((void**)&pp, g_p);
    cudaGetSymbolAddress((void**)&phl, g_hl);
    cudaGetSymbolAddress((void**)&pwf, g_wf);
    cudaGetSymbolAddress((void**)&pwfin, g_wfin);
    cudaGetSymbolAddress((void**)&pcnt, g_cnt);

    // streams/events for graph-level fork/join (host objects, created once; the
    // captured graph is identical on every call — no device allocation involved)
    static cudaStream_t sA = nullptr, sB = nullptr;
    static cudaEvent_t e0 = nullptr, eA = nullptr, eB = nullptr;
    if (!sA) {
        cudaStreamCreateWithFlags(&sA, cudaStreamNonBlocking);
        cudaStreamCreateWithFlags(&sB, cudaStreamNonBlocking);
        cudaEventCreateWithFlags(&e0, cudaEventDisableTiming);
        cudaEventCreateWithFlags(&eA, cudaEventDisableTiming);
        cudaEventCreateWithFlags(&eB, cudaEventDisableTiming);
    }

    const int NB = (NN + 7) / 8;         // warp-per-node blocks
    const int TB64 = (NN + 63) / 64;     // input GEMM blocks (64 rows)
    const int TB128 = (NN + 127) / 128;  // m32 GEMM blocks (128 rows)
    const int SCB = (NN + 255) / 256;    // scan blocks

    // ---- fork ----
    cudaEventRecord(e0, 0);
    cudaStreamWaitEvent(sA, e0, 0);
    cudaStreamWaitEvent(sB, e0, 0);

    // branch A: layer-weight fragments
    prep_weights<<<(6 * HD * HD + 255) / 256, 256, 0, sA>>>(att_w, mlp_w);
    prep_wf<<<(6 * 8 * 16 * 32 + 255) / 256, 256, 0, sA>>>();
    cudaEventRecord(eA, sA);

    // branch B: CSR build
    zeroi_kernel<<<SCB, 256, 0, sB>>>(pcnt, NN);
    hist_kernel<<<(EE + 255) / 256, 256, 0, sB>>>(ei);
    scan1_kernel<<<SCB, 256, 0, sB>>>();
    scan2_kernel<<<1, 256, 0, sB>>>(SCB);
    scan3_kernel<<<SCB, 256, 0, sB>>>();
    scatter_kernel<<<(EE + 255) / 256, 256, 0, sB>>>(ei);
    cudaEventRecord(eB, sB);

    // main branch: input GEMM chain
    prep_win<<<(IN_DIM * HD + 255) / 256, 256>>>(w_in);
    prep_wfin<<<(13 * 16 * 32 + 255) / 256, 256>>>();
    zero4_kernel<<<(GG * 2 * HD / 4 + 255) / 256, 256>>>((float4*)out, GG * 2 * HD / 4);
    gemm_tc_in<<<TB64, 256>>>(x, (const uint4*)pwfin, pp);
    expmap_u_kernel<<<NB, 256>>>(pp, ph, pu, c);

    // ---- join ----
    cudaStreamWaitEvent(0, eA, 0);
    cudaStreamWaitEvent(0, eB, 0);

    for (int l = 0; l < 2; l++) {
        // attention linear: hl = proj(expmap0(u @ W + b))
        gemm_tc128<true><<<TB128, 256>>>(pu, (const uint4*)(pwf + (size_t)l * 8 * 16 * 32 * 4),
                                         att_b + l * DD, pp);
        expmap_kernel<<<NB, 256>>>(pp, phl, c);
        // centroid + GIN combine -> u
        agg_combine_kernel<<<NB, 256>>>(phl, ph, pu, c, eps, l);
        // MLP 0
        gemm_tc128<true><<<TB128, 256>>>(pu, (const uint4*)(pwf + (size_t)(2 + l * 2 + 0) * 8 * 16 * 32 * 4),
                                         mlp_b + (l * 2 + 0) * DD, pp);
        mlp_epi_kernel<false, false><<<NB, 256>>>(pp, nullptr, pu, c, nullptr, nullptr, 0);
        // MLP 1 (+ layer output + pooled readout)
        gemm_tc128<true><<<TB128, 256>>>(pu, (const uint4*)(pwf + (size_t)(2 + l * 2 + 1) * 8 * 16 * 32 * 4),
                                         mlp_b + (l * 2 + 1) * DD, pp);
        mlp_epi_kernel<true, true><<<NB, 256>>>(pp, ph, pu, c, batch, out, l * HD);
    }
}

// round 16
// speedup vs baseline: 1.1185x; 1.0083x over previous
#include <cuda_runtime.h>
#include <math.h>
#include <stdint.h>

#define NN 50000
#define EE 800000
#define IN_DIM 200
#define HD 128
#define DD 127
#define GG 512
#define EPSF 1e-5f

// ---------------- scratch (device globals; no allocation allowed) ----------------
__device__ float g_h[NN * HD];      // hyperboloid node features
__device__ float g_u[NN * HD];      // logmap0 spatial (slots 0..126, slot127 = 0)
__device__ float g_p[NN * HD];      // GEMM output
__device__ float g_hl[NN * HD];     // attention-linear hyperboloid points
__device__ float g_wt[6 * HD * HD];   // transposed+padded weights (k-major)
__device__ float g_wtin[IN_DIM * HD];
__device__ float g_wf[6 * 8 * 16 * 32 * 4];     // bf16-split fragment weights (K=128 mats)
__device__ float g_wfin[13 * 16 * 32 * 4];      // bf16-split fragment input weights (K=200->208)
__device__ int   g_cnt[NN];
__device__ int   g_rowptr[NN + 1];
__device__ int   g_cur[NN];
__device__ int   g_dstidx[EE];
__device__ int   g_blksum[256];
__device__ int   g_blkoff[256];

__device__ __forceinline__ float warp_sum(float v) {
#pragma unroll
    for (int o = 16; o; o >>= 1) v += __shfl_xor_sync(0xffffffffu, v, o);
    return v;
}

__device__ __forceinline__ void red_v4(float* p, float a, float b, float c, float d) {
    asm volatile("red.global.add.v4.f32 [%0], {%1,%2,%3,%4};"
                 :: "l"(p), "f"(a), "f"(b), "f"(c), "f"(d) : "memory");
}

// m16n8k16 bf16 MMA, fp32 accumulate (A row-major frag, B col-major frag)
__device__ __forceinline__ void mma_bf16(float* d, uint32_t a0, uint32_t a1,
                                         uint32_t a2, uint32_t a3,
                                         uint32_t b0, uint32_t b1) {
    asm("mma.sync.aligned.m16n8k16.row.col.f32.bf16.bf16.f32 "
        "{%0,%1,%2,%3}, {%4,%5,%6,%7}, {%8,%9}, {%0,%1,%2,%3};"
        : "+f"(d[0]), "+f"(d[1]), "+f"(d[2]), "+f"(d[3])
        : "r"(a0), "r"(a1), "r"(a2), "r"(a3), "r"(b0), "r"(b1));
}

__device__ __forceinline__ uint32_t bf16x2_hi(float x, float y) {
    uint32_t r;
    asm("cvt.rn.bf16x2.f32 %0, %1, %2;" : "=r"(r) : "f"(y), "f"(x));
    return r;
}
__device__ __forceinline__ uint32_t bf16x2_lo(float x, float y, uint32_t h) {
    float h0 = __uint_as_float(h << 16);
    float h1 = __uint_as_float(h & 0xFFFF0000u);
    return bf16x2_hi(x - h0, y - h1);
}

// ---------------- utility kernels ----------------
__global__ void zero4_kernel(float4* __restrict__ p, int n4) {
    int i = blockIdx.x * blockDim.x + threadIdx.x;
    if (i < n4) p[i] = make_float4(0.f, 0.f, 0.f, 0.f);
}

__global__ void zeroi_kernel(int* __restrict__ p, int n) {
    int i = blockIdx.x * blockDim.x + threadIdx.x;
    if (i < n) p[i] = 0;
}

__global__ void prep_weights(const float* __restrict__ att_w, const float* __restrict__ mlp_w) {
    int idx = blockIdx.x * blockDim.x + threadIdx.x;
    if (idx >= 6 * HD * HD) return;
    int w = idx >> 14;
    int k = (idx >> 7) & 127;
    int j = idx & 127;
    float val = 0.f;
    if (k < DD && j < DD) {
        const float* src = (w < 2) ? (att_w + w * DD * DD) : (mlp_w + (w - 2) * DD * DD);
        val = src[j * DD + k];
    }
    g_wt[idx] = val;
}

__global__ void prep_win(const float* __restrict__ w_in) {
    int idx = blockIdx.x * blockDim.x + threadIdx.x;
    if (idx >= IN_DIM * HD) return;
    int k = idx >> 7;
    int j = idx & 127;
    g_wtin[idx] = (j < DD) ? w_in[k * DD + j] : 0.f;
}

// bf16-split fragment weights: uint4 (b0h, b1h, b0l, b1l) per (mat, k16, tile, lane)
__global__ void prep_wf() {
    int idx = blockIdx.x * blockDim.x + threadIdx.x;
    if (idx >= 6 * 8 * 16 * 32) return;
    int lane = idx & 31;
    int tile = (idx >> 5) & 15;
    int k16 = (idx >> 9) & 7;
    int mat = idx >> 12;
    int gg = lane >> 2, t4 = lane & 3;
    int k0 = k16 * 16 + 2 * t4;
    int n = tile * 8 + gg;
    const float* W = g_wt + mat * HD * HD;
    float w00 = W[k0 * HD + n],       w01 = W[(k0 + 1) * HD + n];
    float w10 = W[(k0 + 8) * HD + n], w11 = W[(k0 + 9) * HD + n];
    uint4 o;
    o.x = bf16x2_hi(w00, w01);
    o.y = bf16x2_hi(w10, w11);
    o.z = bf16x2_lo(w00, w01, o.x);
    o.w = bf16x2_lo(w10, w11, o.y);
    ((uint4*)g_wf)[idx] = o;
}

__global__ void prep_wfin() {
    int idx = blockIdx.x * blockDim.x + threadIdx.x;
    if (idx >= 13 * 16 * 32) return;
    int lane = idx & 31;
    int tile = (idx >> 5) & 15;
    int k16 = idx >> 9;                 // 0..12
    int gg = lane >> 2, t4 = lane & 3;
    int k0 = k16 * 16 + 2 * t4;
    int n = tile * 8 + gg;
    float w00 = (k0 < IN_DIM)     ? g_wtin[k0 * HD + n] : 0.f;
    float w01 = (k0 + 1 < IN_DIM) ? g_wtin[(k0 + 1) * HD + n] : 0.f;
    float w10 = (k0 + 8 < IN_DIM) ? g_wtin[(k0 + 8) * HD + n] : 0.f;
    float w11 = (k0 + 9 < IN_DIM) ? g_wtin[(k0 + 9) * HD + n] : 0.f;
    uint4 o;
    o.x = bf16x2_hi(w00, w01);
    o.y = bf16x2_hi(w10, w11);
    o.z = bf16x2_lo(w00, w01, o.x);
    o.w = bf16x2_lo(w10, w11, o.y);
    ((uint4*)g_wfin)[idx] = o;
}

// ---------------- CSR build ----------------
__global__ void hist_kernel(const int* __restrict__ ei) {
    int e = blockIdx.x * blockDim.x + threadIdx.x;
    if (e < EE) atomicAdd(&g_cnt[ei[e]], 1);
}

__global__ void scan1_kernel() {
    __shared__ int sh[256];
    int t = threadIdx.x;
    int idx = blockIdx.x * 256 + t;
    int v = (idx < NN) ? g_cnt[idx] : 0;
    sh[t] = v;
    __syncthreads();
#pragma unroll
    for (int d = 1; d < 256; d <<= 1) {
        int o = (t >= d) ? sh[t - d] : 0;
        __syncthreads();
        sh[t] += o;
        __syncthreads();
    }
    if (idx < NN) g_rowptr[idx] = sh[t] - v;
    if (t == 255) g_blksum[blockIdx.x] = sh[255];
}

__global__ void scan2_kernel(int nblk) {
    __shared__ int sh[256];
    int t = threadIdx.x;
    int v = (t < nblk) ? g_blksum[t] : 0;
    sh[t] = v;
    __syncthreads();
#pragma unroll
    for (int d = 1; d < 256; d <<= 1) {
        int o = (t >= d) ? sh[t - d] : 0;
        __syncthreads();
        sh[t] += o;
        __syncthreads();
    }
    if (t < nblk) g_blkoff[t] = sh[t] - v;
    if (t == 255) g_rowptr[NN] = sh[255];
}

__global__ void scan3_kernel() {
    int idx = blockIdx.x * 256 + threadIdx.x;
    if (idx >= NN) return;
    int r = g_rowptr[idx] + g_blkoff[blockIdx.x];
    g_rowptr[idx] = r;
    g_cur[idx] = r;
}

__global__ void scatter_kernel(const int* __restrict__ ei) {
    int e = blockIdx.x * blockDim.x + threadIdx.x;
    if (e >= EE) return;
    int s = ei[e];
    int pos = atomicAdd(&g_cur[s], 1);
    g_dstidx[pos] = ei[EE + e];
}

// ---------------- split-bf16 TC GEMM, K=128, m32-per-warp + A prefetch ----------------
// Next k16's 8 raw A float2 loads are issued before the current MMA block so their
// L2 latency overlaps the 48 MMAs. Values/order identical to R12.
template <bool HASBIAS>
__global__ void __launch_bounds__(256, 2) gemm_tc128(const float* __restrict__ U,
                                                     const uint4* __restrict__ WF,
                                                     const float* __restrict__ bias,
                                                     float* __restrict__ P) {
    int tid = threadIdx.x;
    int lane = tid & 31;
    int w = tid >> 5;
    int wm = w & 3;
    int wn = w >> 2;
    int row0 = blockIdx.x * 128;
    int gg = lane >> 2, t4 = lane & 3;
    int ra = row0 + 32 * wm + gg;   // 4 fragment rows: ra, ra+8, ra+16, ra+24
    const float* A0 = U + (size_t)min(ra,      NN - 1) * HD;
    const float* A1 = U + (size_t)min(ra + 8,  NN - 1) * HD;
    const float* A2 = U + (size_t)min(ra + 16, NN - 1) * HD;
    const float* A3 = U + (size_t)min(ra + 24, NN - 1) * HD;

    float acc[8][2][4];   // [n8-tile][m16-half][4]
#pragma unroll
    for (int t = 0; t < 8; t++)
#pragma unroll
        for (int m = 0; m < 2; m++) {
            acc[t][m][0] = 0.f; acc[t][m][1] = 0.f;
            acc[t][m][2] = 0.f; acc[t][m][3] = 0.f;
        }

    // prologue: load k16=0 A values
    float2 c00, c01, c10, c11, c20, c21, c30, c31;
    {
        int c0 = 2 * t4, c1 = c0 + 8;
        c00 = *(const float2*)&A0[c0]; c01 = *(const float2*)&A0[c1];
        c10 = *(const float2*)&A1[c0]; c11 = *(const float2*)&A1[c1];
        c20 = *(const float2*)&A2[c0]; c21 = *(const float2*)&A2[c1];
        c30 = *(const float2*)&A3[c0]; c31 = *(const float2*)&A3[c1];
    }

#pragma unroll
    for (int k16 = 0; k16 < 8; k16++) {
        // prefetch next iteration's A (overlaps this iteration's MMAs)
        float2 n00, n01, n10, n11, n20, n21, n30, n31;
        if (k16 < 7) {
            int c0 = (k16 + 1) * 16 + 2 * t4, c1 = c0 + 8;
            n00 = *(const float2*)&A0[c0]; n01 = *(const float2*)&A0[c1];
            n10 = *(const float2*)&A1[c0]; n11 = *(const float2*)&A1[c1];
            n20 = *(const float2*)&A2[c0]; n21 = *(const float2*)&A2[c1];
            n30 = *(const float2*)&A3[c0]; n31 = *(const float2*)&A3[c1];
        }
        uint32_t h0 = bf16x2_hi(c00.x, c00.y), h1 = bf16x2_hi(c10.x, c10.y);
        uint32_t h2 = bf16x2_hi(c01.x, c01.y), h3 = bf16x2_hi(c11.x, c11.y);
        uint32_t l0 = bf16x2_lo(c00.x, c00.y, h0), l1 = bf16x2_lo(c10.x, c10.y, h1);
        uint32_t l2 = bf16x2_lo(c01.x, c01.y, h2), l3 = bf16x2_lo(c11.x, c11.y, h3);
        uint32_t h4 = bf16x2_hi(c20.x, c20.y), h5 = bf16x2_hi(c30.x, c30.y);
        uint32_t h6 = bf16x2_hi(c21.x, c21.y), h7 = bf16x2_hi(c31.x, c31.y);
        uint32_t l4 = bf16x2_lo(c20.x, c20.y, h4), l5 = bf16x2_lo(c30.x, c30.y, h5);
        uint32_t l6 = bf16x2_lo(c21.x, c21.y, h6), l7 = bf16x2_lo(c31.x, c31.y, h7);
        const uint4* wf = WF + ((size_t)k16 * 16 + wn * 8) * 32 + lane;
#pragma unroll
        for (int t = 0; t < 8; t++) {
            uint4 bv = wf[t * 32];   // (b0h, b1h, b0l, b1l) — reused for both m-halves
            mma_bf16(acc[t][0], h0, h1, h2, h3, bv.x, bv.y);
            mma_bf16(acc[t][0], h0, h1, h2, h3, bv.z, bv.w);
            mma_bf16(acc[t][0], l0, l1, l2, l3, bv.x, bv.y);
            mma_bf16(acc[t][1], h4, h5, h6, h7, bv.x, bv.y);
            mma_bf16(acc[t][1], h4, h5, h6, h7, bv.z, bv.w);
            mma_bf16(acc[t][1], l4, l5, l6, l7, bv.x, bv.y);
        }
        if (k16 < 7) {
            c00 = n00; c01 = n01; c10 = n10; c11 = n11;
            c20 = n20; c21 = n21; c30 = n30; c31 = n31;
        }
    }

#pragma unroll
    for (int t = 0; t < 8; t++) {
        int j0 = 64 * wn + 8 * t + 2 * t4;   // even, 0..126
        float b0 = 0.f, b1 = 0.f;
        if (HASBIAS) {
            b0 = bias[j0];
            b1 = (j0 + 1 < DD) ? bias[j0 + 1] : 0.f;
        }
#pragma unroll
        for (int m = 0; m < 2; m++) {
            float d0 = acc[t][m][0] + b0, d1 = acc[t][m][1] + b1;
            float d2 = acc[t][m][2] + b0, d3 = acc[t][m][3] + b1;
            if (j0 + 1 == 127) { d1 = 0.f; d3 = 0.f; }  // padding col
            int r0 = ra + 16 * m;
            int r1 = r0 + 8;
            if (r0 < NN) *(float2*)&P[(size_t)r0 * HD + j0] = make_float2(d0, d1);
            if (r1 < NN) *(float2*)&P[(size_t)r1 * HD + j0] = make_float2(d2, d3);
        }
    }
}

// ---------------- input GEMM K=200 (direct path, runs once; unchanged) ----------------
__global__ void __launch_bounds__(256) gemm_tc_in(const float* __restrict__ U,
                                                  const uint4* __restrict__ WF,
                                                  float* __restrict__ P) {
    constexpr int K = IN_DIM;
    constexpr int K16 = (K + 15) / 16;   // 13
    int tid = threadIdx.x;
    int lane = tid & 31;
    int w = tid >> 5;
    int wm = w & 3;
    int wn = w >> 2;
    int row0 = blockIdx.x * 64;
    int gg = lane >> 2, t4 = lane & 3;
    int ra = row0 + 16 * wm + gg;
    int rb = ra + 8;
    const float* A0 = U + (size_t)min(ra, NN - 1) * K;
    const float* A1 = U + (size_t)min(rb, NN - 1) * K;

    float acc[8][4];
#pragma unroll
    for (int t = 0; t < 8; t++) {
        acc[t][0] = 0.f; acc[t][1] = 0.f; acc[t][2] = 0.f; acc[t][3] = 0.f;
    }

    for (int k16 = 0; k16 < K16; k16++) {
        int kc = k16 * 16;
        int c0 = kc + 2 * t4;
        int c1 = kc + 8 + 2 * t4;
        float2 fa0, fa1, fa2, fa3;
        if (k16 == K16 - 1) {
            fa0.x = (c0 < K) ? A0[c0] : 0.f;     fa0.y = (c0 + 1 < K) ? A0[c0 + 1] : 0.f;
            fa1.x = (c0 < K) ? A1[c0] : 0.f;     fa1.y = (c0 + 1 < K) ? A1[c0 + 1] : 0.f;
            fa2.x = (c1 < K) ? A0[c1] : 0.f;     fa2.y = (c1 + 1 < K) ? A0[c1 + 1] : 0.f;
            fa3.x = (c1 < K) ? A1[c1] : 0.f;     fa3.y = (c1 + 1 < K) ? A1[c1 + 1] : 0.f;
        } else {
            fa0 = *(const float2*)&A0[c0];
            fa1 = *(const float2*)&A1[c0];
            fa2 = *(const float2*)&A0[c1];
            fa3 = *(const float2*)&A1[c1];
        }
        uint32_t h0 = bf16x2_hi(fa0.x, fa0.y), h1 = bf16x2_hi(fa1.x, fa1.y);
        uint32_t h2 = bf16x2_hi(fa2.x, fa2.y), h3 = bf16x2_hi(fa3.x, fa3.y);
        uint32_t l0 = bf16x2_lo(fa0.x, fa0.y, h0), l1 = bf16x2_lo(fa1.x, fa1.y, h1);
        uint32_t l2 = bf16x2_lo(fa2.x, fa2.y, h2), l3 = bf16x2_lo(fa3.x, fa3.y, h3);
        const uint4* wf = WF + ((size_t)k16 * 16 + wn * 8) * 32 + lane;
#pragma unroll
        for (int t = 0; t < 8; t++) {
            uint4 bv = wf[t * 32];
            mma_bf16(acc[t], h0, h1, h2, h3, bv.x, bv.y);
            mma_bf16(acc[t], h0, h1, h2, h3, bv.z, bv.w);
            mma_bf16(acc[t], l0, l1, l2, l3, bv.x, bv.y);
        }
    }

#pragma unroll
    for (int t = 0; t < 8; t++) {
        int j0 = 64 * wn + 8 * t + 2 * t4;
        float d0 = acc[t][0], d1 = acc[t][1];
        float d2 = acc[t][2], d3 = acc[t][3];
        if (j0 + 1 == 127) { d1 = 0.f; d3 = 0.f; }
        if (ra < NN) *(float2*)&P[(size_t)ra * HD + j0] = make_float2(d0, d1);
        if (rb < NN) *(float2*)&P[(size_t)rb * HD + j0] = make_float2(d2, d3);
    }
}

// ---------------- warp-per-node elementwise kernels (unchanged) ----------------

__device__ __forceinline__ float4 logmap_quad(float4 o, float ss, float x0,
                                              float c, float sc, int lane) {
    float yn = fmaxf(sqrtf(ss), 1e-9f);
    float d = sc * acoshf(fmaxf(x0 / sc, 1.f + EPSF));
    float a = d / yn;
    float nx = __shfl_down_sync(0xffffffffu, o.x, 1);
    float4 u;
    u.x = a * o.y; u.y = a * o.z; u.z = a * o.w;
    u.w = (lane == 31) ? 0.f : a * nx;
    return u;
}

__global__ void expmap_kernel(const float* __restrict__ P, float* __restrict__ out,
                              const float* __restrict__ cptr) {
    int warp = (blockIdx.x * blockDim.x + threadIdx.x) >> 5;
    int lane = threadIdx.x & 31;
    if (warp >= NN) return;
    float c = cptr[0], sc = sqrtf(c);
    float4 v = ((const float4*)(P + (size_t)warp * HD))[lane];
    float s = warp_sum(v.x * v.x + v.y * v.y + v.z * v.z + v.w * v.w);
    float n = fmaxf(sqrtf(s), 1e-9f);
    float sh = sc * sinhf(n / sc) / n;
    float wprev = __shfl_up_sync(0xffffffffu, v.w, 1);
    float4 o;
    o.x = (lane == 0) ? 0.f : sh * wprev;
    o.y = sh * v.x; o.z = sh * v.y; o.w = sh * v.z;
    float ss = warp_sum(((lane == 0) ? 0.f : o.x * o.x) + o.y * o.y + o.z * o.z + o.w * o.w);
    if (lane == 0) o.x = sqrtf(c + ss);
    ((float4*)(out + (size_t)warp * HD))[lane] = o;
}

__global__ void expmap_u_kernel(const float* __restrict__ P, float* __restrict__ H,
                                float* __restrict__ U, const float* __restrict__ cptr) {
    int warp = (blockIdx.x * blockDim.x + threadIdx.x) >> 5;
    int lane = threadIdx.x & 31;
    if (warp >= NN) return;
    float c = cptr[0], sc = sqrtf(c);
    float4 v = ((const float4*)(P + (size_t)warp * HD))[lane];
    float s = warp_sum(v.x * v.x + v.y * v.y + v.z * v.z + v.w * v.w);
    float n = fmaxf(sqrtf(s), 1e-9f);
    float sh = sc * sinhf(n / sc) / n;
    float wprev = __shfl_up_sync(0xffffffffu, v.w, 1);
    float4 o;
    o.x = (lane == 0) ? 0.f : sh * wprev;
    o.y = sh * v.x; o.z = sh * v.y; o.w = sh * v.z;
    float ss = warp_sum(((lane == 0) ? 0.f : o.x * o.x) + o.y * o.y + o.z * o.z + o.w * o.w);
    float x0 = sqrtf(c + ss);
    if (lane == 0) o.x = x0;
    ((float4*)(H + (size_t)warp * HD))[lane] = o;
    ((float4*)(U + (size_t)warp * HD))[lane] = logmap_quad(o, ss, x0, c, sc, lane);
}

// warp per node: CSR centroid (2-edge ILP) + GIN combine; emits u = logmap0(result).
__global__ void agg_combine_kernel(const float* __restrict__ hl, const float* __restrict__ h,
                                   float* __restrict__ U, const float* __restrict__ cptr,
                                   const float* __restrict__ epsp, int l) {
    int warp = (blockIdx.x * blockDim.x + threadIdx.x) >> 5;
    int lane = threadIdx.x & 31;
    if (warp >= NN) return;
    float c = cptr[0], sc = sqrtf(c), ep = epsp[l];
    bool c1 = (sc == 1.f);
    int beg = g_rowptr[warp], end = g_rowptr[warp + 1];
    float4 a = ((const float4*)(hl + (size_t)warp * HD))[lane];
    float ax0 = (lane == 0) ? -a.x : a.x;
    float4 mv = make_float4(0.f, 0.f, 0.f, 0.f);

    int e = beg;
    for (; e + 1 < end; e += 2) {
        int d0i = g_dstidx[e];
        int d1i = g_dstidx[e + 1];
        float4 b0 = ((const float4*)(hl + (size_t)d0i * HD))[lane];
        float4 b1 = ((const float4*)(hl + (size_t)d1i * HD))[lane];
        float4 hv0 = ((const float4*)(h + (size_t)d0i * HD))[lane];
        float4 hv1 = ((const float4*)(h + (size_t)d1i * HD))[lane];
        float p0 = ax0 * b0.x + a.y * b0.y + a.z * b0.z + a.w * b0.w;
        float p1 = ax0 * b1.x + a.y * b1.y + a.z * b1.z + a.w * b1.w;
#pragma unroll
        for (int o = 16; o; o >>= 1) {
            p0 += __shfl_xor_sync(0xffffffffu, p0, o);
            p1 += __shfl_xor_sync(0xffffffffu, p1, o);
        }
        float val0 = fmaxf(-p0 / c, 1.f + EPSF);
        float val1 = fmaxf(-p1 / c, 1.f + EPSF);
        float att0 = c1 ? (1.f / (val0 + sqrtf(val0 * val0 - 1.f)))
                        : expf(-sc * acoshf(val0));
        float att1 = c1 ? (1.f / (val1 + sqrtf(val1 * val1 - 1.f)))
                        : expf(-sc * acoshf(val1));
        mv.x = fmaf(att0, hv0.x, mv.x);
        mv.y = fmaf(att0, hv0.y, mv.y);
        mv.z = fmaf(att0, hv0.z, mv.z);
        mv.w = fmaf(att0, hv0.w, mv.w);
        mv.x = fmaf(att1, hv1.x, mv.x);
        mv.y = fmaf(att1, hv1.y, mv.y);
        mv.z = fmaf(att1, hv1.z, mv.z);
        mv.w = fmaf(att1, hv1.w, mv.w);
    }
    if (e < end) {
        int di = g_dstidx[e];
        float4 b = ((const float4*)(hl + (size_t)di * HD))[lane];
        float4 hv = ((const float4*)(h + (size_t)di * HD))[lane];
        float p = ax0 * b.x + a.y * b.y + a.z * b.z + a.w * b.w;
        p = warp_sum(p);
        float val = fmaxf(-p / c, 1.f + EPSF);
        float att = c1 ? (1.f / (val + sqrtf(val * val - 1.f)))
                       : expf(-sc * acoshf(val));
        mv.x = fmaf(att, hv.x, mv.x);
        mv.y = fmaf(att, hv.y, mv.y);
        mv.z = fmaf(att, hv.z, mv.z);
        mv.w = fmaf(att, hv.w, mv.w);
    }

    float4 hv = ((const float4*)(h + (size_t)warp * HD))[lane];
    float m0 = __shfl_sync(0xffffffffu, mv.x, 0);
    float pm = warp_sum(((lane == 0) ? 0.f : mv.x * mv.x) + mv.y * mv.y + mv.z * mv.z + mv.w * mv.w);
    float denom = sqrtf(fmaxf(m0 * m0 - pm, 1e-9f));
    float r = sc / denom;
    float axx = r * mv.x, ay = r * mv.y, az = r * mv.z, aw = r * mv.w;
    float ssum = warp_sum(((lane == 0) ? 0.f : axx * axx) + ay * ay + az * az + aw * aw);
    float t = sqrtf(c + ssum);
    float yn_a = fmaxf(sqrtf(ssum), 1e-9f);
    float d1 = sc * acoshf(fmaxf(t / sc, 1.f + EPSF));
    float cA = d1 / yn_a;
    float ph = warp_sum(((lane == 0) ? 0.f : hv.x * hv.x) + hv.y * hv.y + hv.z * hv.z + hv.w * hv.w);
    float hp0 = sqrtf(c + ph);
    float yn_h = fmaxf(sqrtf(ph), 1e-9f);
    float d2 = sc * acoshf(fmaxf(hp0 / sc, 1.f + EPSF));
    float cH = (1.f + ep) * d2 / yn_h;
    float4 vv;
    vv.x = (lane == 0) ? 0.f : cA * axx + cH * hv.x;
    vv.y = cA * ay + cH * hv.y;
    vv.z = cA * az + cH * hv.z;
    vv.w = cA * aw + cH * hv.w;
    float pv = warp_sum(vv.x * vv.x + vv.y * vv.y + vv.z * vv.z + vv.w * vv.w);
    float n = fmaxf(sqrtf(pv), 1e-9f);
    float sh = sc * sinhf(n / sc) / n;
    float4 o;
    o.x = (lane == 0) ? 0.f : sh * vv.x;
    o.y = sh * vv.y; o.z = sh * vv.z; o.w = sh * vv.w;
    float so = warp_sum(((lane == 0) ? 0.f : o.x * o.x) + o.y * o.y + o.z * o.z + o.w * o.w);
    float x0 = sqrtf(c + so);
    if (lane == 0) o.x = x0;
    ((float4*)(U + (size_t)warp * HD))[lane] = logmap_quad(o, so, x0, c, sc, lane);
}

template <bool WRITE_H, bool POOL>
__global__ void mlp_epi_kernel(const float* __restrict__ P, float* __restrict__ H,
                               float* __restrict__ U, const float* __restrict__ cptr,
                               const int* __restrict__ batch, float* __restrict__ out,
                               int loff) {
    int warp = (blockIdx.x * blockDim.x + threadIdx.x) >> 5;
    int lane = threadIdx.x & 31;
    if (warp >= NN) return;
    float c = cptr[0], sc = sqrtf(c);
    float4 v = ((const float4*)(P + (size_t)warp * HD))[lane];
    float s = warp_sum(v.x * v.x + v.y * v.y + v.z * v.z + v.w * v.w);
    float n1 = fmaxf(sqrtf(s), 1e-9f);
    float sh1 = sc * sinhf(n1 / sc) / n1;
    float sx = sh1 * v.x, sy = sh1 * v.y, sz = sh1 * v.z, sw = sh1 * v.w;
    float ssum = warp_sum(sx * sx + sy * sy + sz * sz + sw * sw);
    float x0p = sqrtf(c + ssum);
    float ynp = fmaxf(sqrtf(ssum), 1e-9f);
    float dp = sc * acoshf(fmaxf(x0p / sc, 1.f + EPSF));
    float cf = dp / ynp;
    float tx = tanhf(cf * sx), ty = tanhf(cf * sy), tz = tanhf(cf * sz), tw = tanhf(cf * sw);
    float s2 = warp_sum(tx * tx + ty * ty + tz * tz + tw * tw);
    float n2 = fmaxf(sqrtf(s2), 1e-9f);
    float sh2 = sc * sinhf(n2 / sc) / n2;
    float wprev = __shfl_up_sync(0xffffffffu, tw, 1);
    float x0 = sc * coshf(n2 / sc);
    float4 o;
    o.x = (lane == 0) ? x0 : sh2 * wprev;
    o.y = sh2 * tx; o.z = sh2 * ty; o.w = sh2 * tz;
    if (WRITE_H) ((float4*)(H + (size_t)warp * HD))[lane] = o;
    float sl = warp_sum(((lane == 0) ? 0.f : o.x * o.x) + o.y * o.y + o.z * o.z + o.w * o.w);
    float yn = fmaxf(sqrtf(sl), 1e-9f);
    float d = sc * acoshf(fmaxf(x0 / sc, 1.f + EPSF));
    float a = d / yn;
    float nx = __shfl_down_sync(0xffffffffu, o.x, 1);
    float4 u;
    u.x = a * o.y; u.y = a * o.z; u.z = a * o.w;
    u.w = (lane == 31) ? 0.f : a * nx;
    ((float4*)(U + (size_t)warp * HD))[lane] = u;
    if (POOL) {
        int g = batch[warp];
        red_v4(out + (size_t)g * (2 * HD) + loff + lane * 4,
               (lane == 0) ? 0.f : a * o.x, a * o.y, a * o.z, a * o.w);
    }
}

// ---------------- host launcher ----------------
extern "C" void kernel_launch(void* const* d_in, const int* in_sizes, int n_in,
                              void* d_out, int out_size) {
    (void)in_sizes; (void)n_in; (void)out_size;
    const float* x     = (const float*)d_in[0];
    const float* c     = (const float*)d_in[1];
    const float* w_in  = (const float*)d_in[2];
    const float* att_w = (const float*)d_in[3];
    const float* att_b = (const float*)d_in[4];
    const float* eps   = (const float*)d_in[5];
    const float* mlp_w = (const float*)d_in[6];
    const float* mlp_b = (const float*)d_in[7];
    const int*   ei    = (const int*)d_in[8];
    const int*   batch = (const int*)d_in[9];
    float* out = (float*)d_out;

    float *ph, *pu, *pp, *phl, *pwf, *pwfin;
    int* pcnt;
    cudaGetSymbolAddress((void**)&ph, g_h);
    cudaGetSymbolAddress((void**)&pu, g_u);
    cudaGetSymbolAddress((void**)&pp, g_p);
    cudaGetSymbolAddress((void**)&phl, g_hl);
    cudaGetSymbolAddress((void**)&pwf, g_wf);
    cudaGetSymbolAddress((void**)&pwfin, g_wfin);
    cudaGetSymbolAddress((void**)&pcnt, g_cnt);

    // streams/events for graph-level fork/join (host objects, created once)
    static cudaStream_t sA = nullptr, sB = nullptr;
    static cudaEvent_t e0 = nullptr, eA = nullptr, eB = nullptr;
    if (!sA) {
        cudaStreamCreateWithFlags(&sA, cudaStreamNonBlocking);
        cudaStreamCreateWithFlags(&sB, cudaStreamNonBlocking);
        cudaEventCreateWithFlags(&e0, cudaEventDisableTiming);
        cudaEventCreateWithFlags(&eA, cudaEventDisableTiming);
        cudaEventCreateWithFlags(&eB, cudaEventDisableTiming);
    }

    const int NB = (NN + 7) / 8;         // warp-per-node blocks
    const int TB64 = (NN + 63) / 64;     // input GEMM blocks (64 rows)
    const int TB128 = (NN + 127) / 128;  // m32 GEMM blocks (128 rows)
    const int SCB = (NN + 255) / 256;    // scan blocks

    // ---- fork ----
    cudaEventRecord(e0, 0);
    cudaStreamWaitEvent(sA, e0, 0);
    cudaStreamWaitEvent(sB, e0, 0);

    // branch A: layer-weight fragments
    prep_weights<<<(6 * HD * HD + 255) / 256, 256, 0, sA>>>(att_w, mlp_w);
    prep_wf<<<(6 * 8 * 16 * 32 + 255) / 256, 256, 0, sA>>>();
    cudaEventRecord(eA, sA);

    // branch B: CSR build
    zeroi_kernel<<<SCB, 256, 0, sB>>>(pcnt, NN);
    hist_kernel<<<(EE + 255) / 256, 256, 0, sB>>>(ei);
    scan1_kernel<<<SCB, 256, 0, sB>>>();
    scan2_kernel<<<1, 256, 0, sB>>>(SCB);
    scan3_kernel<<<SCB, 256, 0, sB>>>();
    scatter_kernel<<<(EE + 255) / 256, 256, 0, sB>>>(ei);
    cudaEventRecord(eB, sB);

    // main branch: input GEMM chain
    prep_win<<<(IN_DIM * HD + 255) / 256, 256>>>(w_in);
    prep_wfin<<<(13 * 16 * 32 + 255) / 256, 256>>>();
    zero4_kernel<<<(GG * 2 * HD / 4 + 255) / 256, 256>>>((float4*)out, GG * 2 * HD / 4);
    gemm_tc_in<<<TB64, 256>>>(x, (const uint4*)pwfin, pp);
    expmap_u_kernel<<<NB, 256>>>(pp, ph, pu, c);

    // ---- join ----
    cudaStreamWaitEvent(0, eA, 0);
    cudaStreamWaitEvent(0, eB, 0);

    for (int l = 0; l < 2; l++) {
        // attention linear: hl = proj(expmap0(u @ W + b))
        gemm_tc128<true><<<TB128, 256>>>(pu, (const uint4*)(pwf + (size_t)l * 8 * 16 * 32 * 4),
                                         att_b + l * DD, pp);
        expmap_kernel<<<NB, 256>>>(pp, phl, c);
        // centroid + GIN combine -> u
        agg_combine_kernel<<<NB, 256>>>(phl, ph, pu, c, eps, l);
        // MLP 0
        gemm_tc128<true><<<TB128, 256>>>(pu, (const uint4*)(pwf + (size_t)(2 + l * 2 + 0) * 8 * 16 * 32 * 4),
                                         mlp_b + (l * 2 + 0) * DD, pp);
        mlp_epi_kernel<false, false><<<NB, 256>>>(pp, nullptr, pu, c, nullptr, nullptr, 0);
        // MLP 1 (+ layer output + pooled readout)
        gemm_tc128<true><<<TB128, 256>>>(pu, (const uint4*)(pwf + (size_t)(2 + l * 2 + 1) * 8 * 16 * 32 * 4),
                                         mlp_b + (l * 2 + 1) * DD, pp);
        mlp_epi_kernel<true, true><<<NB, 256>>>(pp, ph, pu, c, batch, out, l * HD);
    }
}